// round 1
// baseline (speedup 1.0000x reference)
#include <cuda_runtime.h>
#include <math.h>

#define Bv 4
#define Tv 2048
#define Cv 1024
#define Hv 16
#define Dv 64
#define Mrows (Bv*Tv)   // 8192

// Scratch (device globals; allocation-free per harness rules)
__device__ float g_q[Bv*Hv*Tv*Dv];   // [B,H,T,D]
__device__ float g_k[Bv*Hv*Tv*Dv];
__device__ float g_v[Bv*Hv*Tv*Dv];
__device__ float g_y[Bv*Tv*Cv];      // attention output in [B,T,C]

// ---------------------------------------------------------------------------
// Tiled fp32 GEMM: C[M,N] = A[M,K] @ W[K,N] + bias
// BM=BN=128, BK=16, 256 threads, 8x8 per thread.
// MODE 0: A = x, epilogue scatters into g_q/g_k/g_v head layout (+ bias)
// MODE 1: A = g_y, epilogue writes out[row*N+col] (+ bias)
// ---------------------------------------------------------------------------
template<int MODE>
__global__ void __launch_bounds__(256) gemm_kernel(
    const float* __restrict__ A_in, const float* __restrict__ W,
    const float* __restrict__ bias, float* __restrict__ out,
    int M, int N, int K)
{
    __shared__ float As[16*128];   // transposed: As[k][m]
    __shared__ float Bs[16*128];   // Bs[k][n]

    const float* A = (MODE == 1) ? g_y : A_in;

    const int tid = threadIdx.x;
    const int tx = tid & 15;
    const int ty = tid >> 4;
    const int row0 = blockIdx.y * 128;
    const int col0 = blockIdx.x * 128;

    const int a_r = tid >> 2;          // 0..63
    const int a_c = (tid & 3) << 2;    // 0,4,8,12
    const int b_r = tid >> 5;          // 0..7
    const int b_c = (tid & 31) << 2;   // 0..124

    float acc[8][8];
    #pragma unroll
    for (int i = 0; i < 8; i++)
        #pragma unroll
        for (int j = 0; j < 8; j++) acc[i][j] = 0.f;

    for (int k0 = 0; k0 < K; k0 += 16) {
        #pragma unroll
        for (int p = 0; p < 2; p++) {
            int r = a_r + p * 64;
            float4 a4 = *(const float4*)(A + (size_t)(row0 + r) * K + k0 + a_c);
            As[(a_c + 0) * 128 + r] = a4.x;
            As[(a_c + 1) * 128 + r] = a4.y;
            As[(a_c + 2) * 128 + r] = a4.z;
            As[(a_c + 3) * 128 + r] = a4.w;
        }
        #pragma unroll
        for (int p = 0; p < 2; p++) {
            int r = b_r + p * 8;
            *(float4*)&Bs[r * 128 + b_c] =
                *(const float4*)(W + (size_t)(k0 + r) * N + col0 + b_c);
        }
        __syncthreads();

        #pragma unroll
        for (int kk = 0; kk < 16; kk++) {
            float af[8], bf[8];
            *(float4*)(af)     = *(const float4*)&As[kk * 128 + ty * 8];
            *(float4*)(af + 4) = *(const float4*)&As[kk * 128 + ty * 8 + 4];
            *(float4*)(bf)     = *(const float4*)&Bs[kk * 128 + tx * 8];
            *(float4*)(bf + 4) = *(const float4*)&Bs[kk * 128 + tx * 8 + 4];
            #pragma unroll
            for (int i = 0; i < 8; i++)
                #pragma unroll
                for (int j = 0; j < 8; j++)
                    acc[i][j] = fmaf(af[i], bf[j], acc[i][j]);
        }
        __syncthreads();
    }

    #pragma unroll
    for (int i = 0; i < 8; i++) {
        int row = row0 + ty * 8 + i;
        #pragma unroll
        for (int jv = 0; jv < 2; jv++) {
            int col = col0 + tx * 8 + jv * 4;
            float4 v;
            v.x = acc[i][jv * 4 + 0] + bias[col + 0];
            v.y = acc[i][jv * 4 + 1] + bias[col + 1];
            v.z = acc[i][jv * 4 + 2] + bias[col + 2];
            v.w = acc[i][jv * 4 + 3] + bias[col + 3];
            if (MODE == 0) {
                int which = col >> 10;          // 0=q,1=k,2=v
                int cc = col & 1023;
                int h = cc >> 6, d = cc & 63;
                int b = row >> 11, t = row & 2047;
                float* dst = (which == 0) ? g_q : (which == 1) ? g_k : g_v;
                *(float4*)&dst[((size_t)((b * Hv + h) * Tv + t)) * Dv + d] = v;
            } else {
                *(float4*)&out[(size_t)row * N + col] = v;
            }
        }
    }
}

// ---------------------------------------------------------------------------
// Flash attention, fp32, causal. 64x64 tiles, D=64. 256 threads, 4x4/thread.
// Smem: Qs | KP (K-transposed, later P overlay) | Vs  == exactly 48 KB.
// ---------------------------------------------------------------------------
__global__ void __launch_bounds__(256) attn_kernel()
{
    __shared__ float Qs[64 * 64];
    __shared__ float KP[64 * 64];
    __shared__ float Vs[64 * 64];

    const int tid = threadIdx.x;
    const int tx = tid & 15;
    const int ty = tid >> 4;
    const int bh = blockIdx.y;                 // b*H + head
    const int m0 = blockIdx.x * 64;

    const float* qp = g_q + (size_t)bh * Tv * Dv;
    const float* kp = g_k + (size_t)bh * Tv * Dv;
    const float* vp = g_v + (size_t)bh * Tv * Dv;

    const int lr = tid >> 2;                   // 0..63
    const int lc = (tid & 3) * 16;             // 0,16,32,48

    // Load Q tile, pre-scaled by 1/sqrt(D)
    #pragma unroll
    for (int v = 0; v < 4; v++) {
        float4 t4 = *(const float4*)(qp + (size_t)(m0 + lr) * Dv + lc + v * 4);
        int base = lr * 64 + lc + v * 4;
        Qs[base + 0] = t4.x * 0.125f;
        Qs[base + 1] = t4.y * 0.125f;
        Qs[base + 2] = t4.z * 0.125f;
        Qs[base + 3] = t4.w * 0.125f;
    }

    float m_i[4], l_i[4], o[4][4];
    #pragma unroll
    for (int i = 0; i < 4; i++) {
        m_i[i] = -1e30f; l_i[i] = 0.f;
        #pragma unroll
        for (int j = 0; j < 4; j++) o[i][j] = 0.f;
    }

    for (int j0 = 0; j0 <= m0; j0 += 64) {
        // Load K (transposed -> KP[k][col]) and V (direct -> Vs[row][d])
        #pragma unroll
        for (int v = 0; v < 4; v++) {
            float4 k4 = *(const float4*)(kp + (size_t)(j0 + lr) * Dv + lc + v * 4);
            KP[(lc + v * 4 + 0) * 64 + lr] = k4.x;
            KP[(lc + v * 4 + 1) * 64 + lr] = k4.y;
            KP[(lc + v * 4 + 2) * 64 + lr] = k4.z;
            KP[(lc + v * 4 + 3) * 64 + lr] = k4.w;
            float4 v4 = *(const float4*)(vp + (size_t)(j0 + lr) * Dv + lc + v * 4);
            *(float4*)&Vs[lr * 64 + lc + v * 4] = v4;
        }
        __syncthreads();   // tiles ready (also covers Q on first iter)

        // S = Q @ K^T (4x4 per thread)
        float s[4][4];
        #pragma unroll
        for (int i = 0; i < 4; i++)
            #pragma unroll
            for (int j = 0; j < 4; j++) s[i][j] = 0.f;

        #pragma unroll 8
        for (int kk = 0; kk < 64; kk++) {
            float4 kv = *(const float4*)&KP[kk * 64 + tx * 4];
            #pragma unroll
            for (int i = 0; i < 4; i++) {
                float q = Qs[(ty * 4 + i) * 64 + kk];
                s[i][0] = fmaf(q, kv.x, s[i][0]);
                s[i][1] = fmaf(q, kv.y, s[i][1]);
                s[i][2] = fmaf(q, kv.z, s[i][2]);
                s[i][3] = fmaf(q, kv.w, s[i][3]);
            }
        }

        // Causal mask (only the diagonal tile needs it)
        if (j0 == m0) {
            #pragma unroll
            for (int i = 0; i < 4; i++)
                #pragma unroll
                for (int j = 0; j < 4; j++)
                    if (tx * 4 + j > ty * 4 + i) s[i][j] = -1e30f;
        }

        // Online softmax (row stats across the 16 lanes sharing ty)
        #pragma unroll
        for (int i = 0; i < 4; i++) {
            float mx = fmaxf(fmaxf(s[i][0], s[i][1]), fmaxf(s[i][2], s[i][3]));
            #pragma unroll
            for (int msk = 8; msk > 0; msk >>= 1)
                mx = fmaxf(mx, __shfl_xor_sync(0xffffffffu, mx, msk));
            float mn = fmaxf(m_i[i], mx);
            float corr = __expf(m_i[i] - mn);
            m_i[i] = mn;
            float rs = 0.f;
            #pragma unroll
            for (int j = 0; j < 4; j++) {
                float p = __expf(s[i][j] - mn);
                s[i][j] = p;
                rs += p;
            }
            #pragma unroll
            for (int msk = 8; msk > 0; msk >>= 1)
                rs += __shfl_xor_sync(0xffffffffu, rs, msk);
            l_i[i] = l_i[i] * corr + rs;
            #pragma unroll
            for (int j = 0; j < 4; j++) o[i][j] *= corr;
        }

        __syncthreads();   // everyone done reading KP-as-K
        #pragma unroll
        for (int i = 0; i < 4; i++)
            *(float4*)&KP[(ty * 4 + i) * 64 + tx * 4] =
                make_float4(s[i][0], s[i][1], s[i][2], s[i][3]);
        __syncthreads();   // P ready

        // O += P @ V
        #pragma unroll 8
        for (int jj = 0; jj < 64; jj++) {
            float4 vv = *(const float4*)&Vs[jj * 64 + tx * 4];
            #pragma unroll
            for (int i = 0; i < 4; i++) {
                float p = KP[(ty * 4 + i) * 64 + jj];
                o[i][0] = fmaf(p, vv.x, o[i][0]);
                o[i][1] = fmaf(p, vv.y, o[i][1]);
                o[i][2] = fmaf(p, vv.z, o[i][2]);
                o[i][3] = fmaf(p, vv.w, o[i][3]);
            }
        }
        __syncthreads();   // done with Vs/KP before next tile load
    }

    // Normalize and write to g_y in [B,T,C] layout (head-merged)
    const int b = bh >> 4;
    const int head = bh & 15;
    #pragma unroll
    for (int i = 0; i < 4; i++) {
        float inv = 1.f / l_i[i];
        int m = m0 + ty * 4 + i;
        float4 r;
        r.x = o[i][0] * inv;
        r.y = o[i][1] * inv;
        r.z = o[i][2] * inv;
        r.w = o[i][3] * inv;
        *(float4*)&g_y[((size_t)(b * Tv + m)) * Cv + head * 64 + tx * 4] = r;
    }
}

// ---------------------------------------------------------------------------
extern "C" void kernel_launch(void* const* d_in, const int* in_sizes, int n_in,
                              void* d_out, int out_size)
{
    const float* x     = (const float*)d_in[0];
    const float* W_qkv = (const float*)d_in[1];
    const float* b_qkv = (const float*)d_in[2];
    const float* W_out = (const float*)d_in[3];
    const float* b_out = (const float*)d_in[4];
    float* out = (float*)d_out;

    dim3 blk(256);

    // 1) QKV projection with head scatter: [8192,1024] @ [1024,3072]
    gemm_kernel<0><<<dim3(3 * Cv / 128, Mrows / 128), blk>>>(
        x, W_qkv, b_qkv, nullptr, Mrows, 3 * Cv, Cv);

    // 2) Causal flash attention per (head, q-tile)
    attn_kernel<<<dim3(Tv / 64, Bv * Hv), blk>>>();

    // 3) Output projection: [8192,1024] @ [1024,1024]
    gemm_kernel<1><<<dim3(Cv / 128, Mrows / 128), blk>>>(
        nullptr, W_out, b_out, out, Mrows, Cv, Cv);
}

// round 3
// speedup vs baseline: 1.6670x; 1.6670x over previous
#include <cuda_runtime.h>
#include <math.h>
#include <stdint.h>

#define Bv 4
#define Tv 2048
#define Cv 1024
#define Hv 16
#define Dv 64
#define Mrows (Bv*Tv)   // 8192

// ---------------- scratch (device globals; allocation-free) ----------------
__device__ float g_q[Bv*Hv*Tv*Dv];    // [B,H,T,D]
__device__ float g_k[Bv*Hv*Tv*Dv];
__device__ float g_v[Bv*Hv*Tv*Dv];
__device__ float g_y[Bv*Tv*Cv];       // attention output [B,T,C]
__device__ float g_wqkvT[3*Cv*Cv];    // W_qkv^T [3072][1024]
__device__ float g_woutT[Cv*Cv];      // W_out^T [1024][1024]

__device__ __forceinline__ float rna_tf32(float x) {
    uint32_t u;
    asm("cvt.rna.tf32.f32 %0, %1;" : "=r"(u) : "f"(x));
    return __uint_as_float(u);
}

// m16n8k8 tf32 warp MMA (baseline PTX feature — no 'a' target needed)
__device__ __forceinline__ void mma16n8k8(float* c, const uint32_t* a, const uint32_t* b) {
    asm volatile(
        "mma.sync.aligned.m16n8k8.row.col.f32.tf32.tf32.f32 "
        "{%0,%1,%2,%3}, {%4,%5,%6,%7}, {%8,%9}, {%0,%1,%2,%3};"
        : "+f"(c[0]), "+f"(c[1]), "+f"(c[2]), "+f"(c[3])
        : "r"(a[0]), "r"(a[1]), "r"(a[2]), "r"(a[3]), "r"(b[0]), "r"(b[1]));
}

// ---------------- prep: plain weight transpose (rounding done in GEMM) ------
__global__ void transpose_kernel(const float* __restrict__ src, float* __restrict__ dst,
                                 int R, int C) {
    __shared__ float t[32][33];
    int c0 = blockIdx.x * 32, r0 = blockIdx.y * 32;
    #pragma unroll
    for (int i = 0; i < 32; i += 8)
        t[threadIdx.y + i][threadIdx.x] =
            src[(size_t)(r0 + threadIdx.y + i) * C + c0 + threadIdx.x];
    __syncthreads();
    #pragma unroll
    for (int i = 0; i < 32; i += 8)
        dst[(size_t)(c0 + threadIdx.y + i) * R + r0 + threadIdx.x] =
            t[threadIdx.x][threadIdx.y + i];
}

// ---------------------------------------------------------------------------
// tf32 warp-MMA GEMM: C[M,N] = A[M,1024] @ Wt[N,1024]^T + bias
// CTA 128x128, BK=32, 256 threads (8 warps, 2x4), warp tile 64x32.
// Register-prefetch double buffer. Operands rna-rounded to tf32 at STS.
// MODE 0: scatter into g_q/g_k/g_v.  MODE 1: out[row*1024+col].
// ---------------------------------------------------------------------------
#define BK 32
#define LDW 36   // padded smem row stride (words)

template<int MODE>
__global__ void __launch_bounds__(256) gemm_mma(
    const float* __restrict__ A_in, const float* __restrict__ Wt,
    const float* __restrict__ bias, float* __restrict__ out)
{
    __shared__ float As[128 * LDW];
    __shared__ float Bs[128 * LDW];

    const float* A = (MODE == 1) ? g_y : A_in;

    const int tid  = threadIdx.x;
    const int lane = tid & 31;
    const int wid  = tid >> 5;
    const int wm   = (wid & 1) * 64;       // warp m-offset in CTA tile
    const int wn   = (wid >> 1) * 32;      // warp n-offset
    const int g    = lane >> 2;            // groupID
    const int tg   = lane & 3;             // threadID_in_group

    const int row0 = blockIdx.y * 128;
    const int col0 = blockIdx.x * 128;
    const float* Ab = A  + (size_t)row0 * Cv;
    const float* Bb = Wt + (size_t)col0 * Cv;

    // granule mapping: float4 f = i*256+tid -> r=f>>3, kc=(f&7)*4
    const int gr = tid >> 3;
    const int gc = (tid & 7) << 2;

    float c[4][4][4];
    #pragma unroll
    for (int mt = 0; mt < 4; mt++)
        #pragma unroll
        for (int nt = 0; nt < 4; nt++)
            #pragma unroll
            for (int i = 0; i < 4; i++) c[mt][nt][i] = 0.f;

    float4 pa[4], pb[4];
    #pragma unroll
    for (int i = 0; i < 4; i++) {
        int r = gr + i * 32;
        pa[i] = *(const float4*)(Ab + (size_t)r * Cv + gc);
        pb[i] = *(const float4*)(Bb + (size_t)r * Cv + gc);
    }

    const uint32_t* Asu = (const uint32_t*)As;
    const uint32_t* Bsu = (const uint32_t*)Bs;

    for (int ch = 0; ch < Cv / BK; ch++) {
        // store prefetched chunk (tf32-rounded)
        #pragma unroll
        for (int i = 0; i < 4; i++) {
            int r = gr + i * 32;
            float4 va = pa[i], vb = pb[i];
            va.x = rna_tf32(va.x); va.y = rna_tf32(va.y);
            va.z = rna_tf32(va.z); va.w = rna_tf32(va.w);
            vb.x = rna_tf32(vb.x); vb.y = rna_tf32(vb.y);
            vb.z = rna_tf32(vb.z); vb.w = rna_tf32(vb.w);
            *(float4*)&As[r * LDW + gc] = va;
            *(float4*)&Bs[r * LDW + gc] = vb;
        }
        __syncthreads();

        // prefetch next chunk (overlaps with compute below)
        if (ch + 1 < Cv / BK) {
            const float* gA = Ab + (ch + 1) * BK;
            const float* gB = Bb + (ch + 1) * BK;
            #pragma unroll
            for (int i = 0; i < 4; i++) {
                int r = gr + i * 32;
                pa[i] = *(const float4*)(gA + (size_t)r * Cv + gc);
                pb[i] = *(const float4*)(gB + (size_t)r * Cv + gc);
            }
        }

        // 4 k-steps of 8
        #pragma unroll
        for (int ks = 0; ks < 4; ks++) {
            const int kk = ks * 8 + tg;
            uint32_t a[4][4];
            #pragma unroll
            for (int mt = 0; mt < 4; mt++) {
                const int r = wm + mt * 16 + g;
                a[mt][0] = Asu[r * LDW + kk];
                a[mt][1] = Asu[(r + 8) * LDW + kk];
                a[mt][2] = Asu[r * LDW + kk + 4];
                a[mt][3] = Asu[(r + 8) * LDW + kk + 4];
            }
            uint32_t b[4][2];
            #pragma unroll
            for (int nt = 0; nt < 4; nt++) {
                const int n = wn + nt * 8 + g;
                b[nt][0] = Bsu[n * LDW + kk];
                b[nt][1] = Bsu[n * LDW + kk + 4];
            }
            #pragma unroll
            for (int mt = 0; mt < 4; mt++)
                #pragma unroll
                for (int nt = 0; nt < 4; nt++)
                    mma16n8k8(c[mt][nt], a[mt], b[nt]);
        }
        __syncthreads();
    }

    // epilogue: c0,c1 -> (row, 2tg/2tg+1); c2,c3 -> row+8
    #pragma unroll
    for (int mt = 0; mt < 4; mt++) {
        #pragma unroll
        for (int r2 = 0; r2 < 2; r2++) {
            const int row = row0 + wm + mt * 16 + g + r2 * 8;
            const int b_ = row >> 11, t_ = row & 2047;
            #pragma unroll
            for (int nt = 0; nt < 4; nt++) {
                const int col = col0 + wn + nt * 8 + tg * 2;
                float2 v;
                v.x = c[mt][nt][r2 * 2 + 0] + __ldg(bias + col + 0);
                v.y = c[mt][nt][r2 * 2 + 1] + __ldg(bias + col + 1);
                if (MODE == 0) {
                    const int which = col >> 10;       // 0=q,1=k,2=v
                    const int cc = col & 1023;
                    const int h = cc >> 6, d = cc & 63;
                    float* dst = (which == 0) ? g_q : (which == 1) ? g_k : g_v;
                    *(float2*)&dst[((size_t)((b_ * Hv + h) * Tv + t_)) * Dv + d] = v;
                } else {
                    *(float2*)&out[(size_t)row * Cv + col] = v;
                }
            }
        }
    }
}

// ---------------------------------------------------------------------------
// Flash attention, fp32, causal. 64x64 tiles, D=64. 256 threads, 4x4/thread.
// ---------------------------------------------------------------------------
__global__ void __launch_bounds__(256) attn_kernel()
{
    __shared__ float Qs[64 * 64];
    __shared__ float KP[64 * 64];
    __shared__ float Vs[64 * 64];

    const int tid = threadIdx.x;
    const int tx = tid & 15;
    const int ty = tid >> 4;
    const int bh = blockIdx.y;
    const int m0 = blockIdx.x * 64;

    const float* qp = g_q + (size_t)bh * Tv * Dv;
    const float* kp = g_k + (size_t)bh * Tv * Dv;
    const float* vp = g_v + (size_t)bh * Tv * Dv;

    const int lr = tid >> 2;
    const int lc = (tid & 3) * 16;

    #pragma unroll
    for (int v = 0; v < 4; v++) {
        float4 t4 = *(const float4*)(qp + (size_t)(m0 + lr) * Dv + lc + v * 4);
        int base = lr * 64 + lc + v * 4;
        Qs[base + 0] = t4.x * 0.125f;
        Qs[base + 1] = t4.y * 0.125f;
        Qs[base + 2] = t4.z * 0.125f;
        Qs[base + 3] = t4.w * 0.125f;
    }

    float m_i[4], l_i[4], o[4][4];
    #pragma unroll
    for (int i = 0; i < 4; i++) {
        m_i[i] = -1e30f; l_i[i] = 0.f;
        #pragma unroll
        for (int j = 0; j < 4; j++) o[i][j] = 0.f;
    }

    for (int j0 = 0; j0 <= m0; j0 += 64) {
        #pragma unroll
        for (int v = 0; v < 4; v++) {
            float4 k4 = *(const float4*)(kp + (size_t)(j0 + lr) * Dv + lc + v * 4);
            KP[(lc + v * 4 + 0) * 64 + lr] = k4.x;
            KP[(lc + v * 4 + 1) * 64 + lr] = k4.y;
            KP[(lc + v * 4 + 2) * 64 + lr] = k4.z;
            KP[(lc + v * 4 + 3) * 64 + lr] = k4.w;
            float4 v4 = *(const float4*)(vp + (size_t)(j0 + lr) * Dv + lc + v * 4);
            *(float4*)&Vs[lr * 64 + lc + v * 4] = v4;
        }
        __syncthreads();

        float s[4][4];
        #pragma unroll
        for (int i = 0; i < 4; i++)
            #pragma unroll
            for (int j = 0; j < 4; j++) s[i][j] = 0.f;

        #pragma unroll 8
        for (int kk = 0; kk < 64; kk++) {
            float4 kv = *(const float4*)&KP[kk * 64 + tx * 4];
            #pragma unroll
            for (int i = 0; i < 4; i++) {
                float q = Qs[(ty * 4 + i) * 64 + kk];
                s[i][0] = fmaf(q, kv.x, s[i][0]);
                s[i][1] = fmaf(q, kv.y, s[i][1]);
                s[i][2] = fmaf(q, kv.z, s[i][2]);
                s[i][3] = fmaf(q, kv.w, s[i][3]);
            }
        }

        if (j0 == m0) {
            #pragma unroll
            for (int i = 0; i < 4; i++)
                #pragma unroll
                for (int j = 0; j < 4; j++)
                    if (tx * 4 + j > ty * 4 + i) s[i][j] = -1e30f;
        }

        #pragma unroll
        for (int i = 0; i < 4; i++) {
            float mx = fmaxf(fmaxf(s[i][0], s[i][1]), fmaxf(s[i][2], s[i][3]));
            #pragma unroll
            for (int msk = 8; msk > 0; msk >>= 1)
                mx = fmaxf(mx, __shfl_xor_sync(0xffffffffu, mx, msk));
            float mn = fmaxf(m_i[i], mx);
            float corr = __expf(m_i[i] - mn);
            m_i[i] = mn;
            float rs = 0.f;
            #pragma unroll
            for (int j = 0; j < 4; j++) {
                float p = __expf(s[i][j] - mn);
                s[i][j] = p;
                rs += p;
            }
            #pragma unroll
            for (int msk = 8; msk > 0; msk >>= 1)
                rs += __shfl_xor_sync(0xffffffffu, rs, msk);
            l_i[i] = l_i[i] * corr + rs;
            #pragma unroll
            for (int j = 0; j < 4; j++) o[i][j] *= corr;
        }

        __syncthreads();
        #pragma unroll
        for (int i = 0; i < 4; i++)
            *(float4*)&KP[(ty * 4 + i) * 64 + tx * 4] =
                make_float4(s[i][0], s[i][1], s[i][2], s[i][3]);
        __syncthreads();

        #pragma unroll 8
        for (int jj = 0; jj < 64; jj++) {
            float4 vv = *(const float4*)&Vs[jj * 64 + tx * 4];
            #pragma unroll
            for (int i = 0; i < 4; i++) {
                float p = KP[(ty * 4 + i) * 64 + jj];
                o[i][0] = fmaf(p, vv.x, o[i][0]);
                o[i][1] = fmaf(p, vv.y, o[i][1]);
                o[i][2] = fmaf(p, vv.z, o[i][2]);
                o[i][3] = fmaf(p, vv.w, o[i][3]);
            }
        }
        __syncthreads();
    }

    const int b = bh >> 4;
    const int head = bh & 15;
    #pragma unroll
    for (int i = 0; i < 4; i++) {
        float inv = 1.f / l_i[i];
        int m = m0 + ty * 4 + i;
        float4 r;
        r.x = o[i][0] * inv;
        r.y = o[i][1] * inv;
        r.z = o[i][2] * inv;
        r.w = o[i][3] * inv;
        *(float4*)&g_y[((size_t)(b * Tv + m)) * Cv + head * 64 + tx * 4] = r;
    }
}

// ---------------------------------------------------------------------------
extern "C" void kernel_launch(void* const* d_in, const int* in_sizes, int n_in,
                              void* d_out, int out_size)
{
    const float* x     = (const float*)d_in[0];
    const float* W_qkv = (const float*)d_in[1];
    const float* b_qkv = (const float*)d_in[2];
    const float* W_out = (const float*)d_in[3];
    const float* b_out = (const float*)d_in[4];
    float* out = (float*)d_out;

    float* wqT; cudaGetSymbolAddress((void**)&wqT, g_wqkvT);
    float* woT; cudaGetSymbolAddress((void**)&woT, g_woutT);

    // prep: transpose weights to [N][K]
    transpose_kernel<<<dim3(3 * Cv / 32, Cv / 32), dim3(32, 8)>>>(W_qkv, wqT, Cv, 3 * Cv);
    transpose_kernel<<<dim3(Cv / 32, Cv / 32), dim3(32, 8)>>>(W_out, woT, Cv, Cv);

    // 1) QKV projection (tf32 warp MMA) with head scatter
    gemm_mma<0><<<dim3(3 * Cv / 128, Mrows / 128), 256>>>(x, wqT, b_qkv, nullptr);

    // 2) causal flash attention (SIMT fp32)
    attn_kernel<<<dim3(Tv / 64, Bv * Hv), 256>>>();

    // 3) output projection (tf32 warp MMA)
    gemm_mma<1><<<dim3(Cv / 128, Mrows / 128), 256>>>(nullptr, woT, b_out, out);
}

// round 4
// speedup vs baseline: 3.0008x; 1.8001x over previous
#include <cuda_runtime.h>
#include <math.h>
#include <stdint.h>

#define Bv 4
#define Tv 2048
#define Cv 1024
#define Hv 16
#define Dv 64
#define Mrows (Bv*Tv)   // 8192

// ---------------- scratch (device globals; allocation-free) ----------------
__device__ float g_q[Bv*Hv*Tv*Dv];    // [B,H,T,D]
__device__ float g_k[Bv*Hv*Tv*Dv];
__device__ float g_v[Bv*Hv*Tv*Dv];
__device__ float g_y[Bv*Tv*Cv];       // attention output [B,T,C]
__device__ float g_wqkvT[3*Cv*Cv];    // W_qkv^T [3072][1024]
__device__ float g_woutT[Cv*Cv];      // W_out^T [1024][1024]

__device__ __forceinline__ float rna_tf32(float x) {
    uint32_t u;
    asm("cvt.rna.tf32.f32 %0, %1;" : "=r"(u) : "f"(x));
    return __uint_as_float(u);
}

// m16n8k8 tf32 warp MMA (baseline PTX feature, validated in Round 3)
__device__ __forceinline__ void mma16n8k8(float* c, const uint32_t* a, const uint32_t* b) {
    asm volatile(
        "mma.sync.aligned.m16n8k8.row.col.f32.tf32.tf32.f32 "
        "{%0,%1,%2,%3}, {%4,%5,%6,%7}, {%8,%9}, {%0,%1,%2,%3};"
        : "+f"(c[0]), "+f"(c[1]), "+f"(c[2]), "+f"(c[3])
        : "r"(a[0]), "r"(a[1]), "r"(a[2]), "r"(a[3]), "r"(b[0]), "r"(b[1]));
}

// ---------------- prep: weight transpose ----------------
__global__ void transpose_kernel(const float* __restrict__ src, float* __restrict__ dst,
                                 int R, int C) {
    __shared__ float t[32][33];
    int c0 = blockIdx.x * 32, r0 = blockIdx.y * 32;
    #pragma unroll
    for (int i = 0; i < 32; i += 8)
        t[threadIdx.y + i][threadIdx.x] =
            src[(size_t)(r0 + threadIdx.y + i) * C + c0 + threadIdx.x];
    __syncthreads();
    #pragma unroll
    for (int i = 0; i < 32; i += 8)
        dst[(size_t)(c0 + threadIdx.y + i) * R + r0 + threadIdx.x] =
            t[threadIdx.x][threadIdx.y + i];
}

// ---------------------------------------------------------------------------
// tf32 warp-MMA GEMM (unchanged from Round 3, validated)
// ---------------------------------------------------------------------------
#define BK 32
#define LDW 36

template<int MODE>
__global__ void __launch_bounds__(256) gemm_mma(
    const float* __restrict__ A_in, const float* __restrict__ Wt,
    const float* __restrict__ bias, float* __restrict__ out)
{
    __shared__ float As[128 * LDW];
    __shared__ float Bs[128 * LDW];

    const float* A = (MODE == 1) ? g_y : A_in;

    const int tid  = threadIdx.x;
    const int lane = tid & 31;
    const int wid  = tid >> 5;
    const int wm   = (wid & 1) * 64;
    const int wn   = (wid >> 1) * 32;
    const int g    = lane >> 2;
    const int tg   = lane & 3;

    const int row0 = blockIdx.y * 128;
    const int col0 = blockIdx.x * 128;
    const float* Ab = A  + (size_t)row0 * Cv;
    const float* Bb = Wt + (size_t)col0 * Cv;

    const int gr = tid >> 3;
    const int gc = (tid & 7) << 2;

    float c[4][4][4];
    #pragma unroll
    for (int mt = 0; mt < 4; mt++)
        #pragma unroll
        for (int nt = 0; nt < 4; nt++)
            #pragma unroll
            for (int i = 0; i < 4; i++) c[mt][nt][i] = 0.f;

    float4 pa[4], pb[4];
    #pragma unroll
    for (int i = 0; i < 4; i++) {
        int r = gr + i * 32;
        pa[i] = *(const float4*)(Ab + (size_t)r * Cv + gc);
        pb[i] = *(const float4*)(Bb + (size_t)r * Cv + gc);
    }

    const uint32_t* Asu = (const uint32_t*)As;
    const uint32_t* Bsu = (const uint32_t*)Bs;

    for (int ch = 0; ch < Cv / BK; ch++) {
        #pragma unroll
        for (int i = 0; i < 4; i++) {
            int r = gr + i * 32;
            float4 va = pa[i], vb = pb[i];
            va.x = rna_tf32(va.x); va.y = rna_tf32(va.y);
            va.z = rna_tf32(va.z); va.w = rna_tf32(va.w);
            vb.x = rna_tf32(vb.x); vb.y = rna_tf32(vb.y);
            vb.z = rna_tf32(vb.z); vb.w = rna_tf32(vb.w);
            *(float4*)&As[r * LDW + gc] = va;
            *(float4*)&Bs[r * LDW + gc] = vb;
        }
        __syncthreads();

        if (ch + 1 < Cv / BK) {
            const float* gA = Ab + (ch + 1) * BK;
            const float* gB = Bb + (ch + 1) * BK;
            #pragma unroll
            for (int i = 0; i < 4; i++) {
                int r = gr + i * 32;
                pa[i] = *(const float4*)(gA + (size_t)r * Cv + gc);
                pb[i] = *(const float4*)(gB + (size_t)r * Cv + gc);
            }
        }

        #pragma unroll
        for (int ks = 0; ks < 4; ks++) {
            const int kk = ks * 8 + tg;
            uint32_t a[4][4];
            #pragma unroll
            for (int mt = 0; mt < 4; mt++) {
                const int r = wm + mt * 16 + g;
                a[mt][0] = Asu[r * LDW + kk];
                a[mt][1] = Asu[(r + 8) * LDW + kk];
                a[mt][2] = Asu[r * LDW + kk + 4];
                a[mt][3] = Asu[(r + 8) * LDW + kk + 4];
            }
            uint32_t b[4][2];
            #pragma unroll
            for (int nt = 0; nt < 4; nt++) {
                const int n = wn + nt * 8 + g;
                b[nt][0] = Bsu[n * LDW + kk];
                b[nt][1] = Bsu[n * LDW + kk + 4];
            }
            #pragma unroll
            for (int mt = 0; mt < 4; mt++)
                #pragma unroll
                for (int nt = 0; nt < 4; nt++)
                    mma16n8k8(c[mt][nt], a[mt], b[nt]);
        }
        __syncthreads();
    }

    #pragma unroll
    for (int mt = 0; mt < 4; mt++) {
        #pragma unroll
        for (int r2 = 0; r2 < 2; r2++) {
            const int row = row0 + wm + mt * 16 + g + r2 * 8;
            const int b_ = row >> 11, t_ = row & 2047;
            #pragma unroll
            for (int nt = 0; nt < 4; nt++) {
                const int col = col0 + wn + nt * 8 + tg * 2;
                float2 v;
                v.x = c[mt][nt][r2 * 2 + 0] + __ldg(bias + col + 0);
                v.y = c[mt][nt][r2 * 2 + 1] + __ldg(bias + col + 1);
                if (MODE == 0) {
                    const int which = col >> 10;
                    const int cc = col & 1023;
                    const int h = cc >> 6, d = cc & 63;
                    float* dst = (which == 0) ? g_q : (which == 1) ? g_k : g_v;
                    *(float2*)&dst[((size_t)((b_ * Hv + h) * Tv + t_)) * Dv + d] = v;
                } else {
                    *(float2*)&out[(size_t)row * Cv + col] = v;
                }
            }
        }
    }
}

// ---------------------------------------------------------------------------
// Flash attention on mma.sync tf32. CTA: 128 q-rows x 64 keys/iter.
// 8 warps x 16 rows. Smem stride 68 words -> conflict-free fragment LDS.
// Per-warp-private P staging: softmax -> PV needs only __syncwarp.
// ---------------------------------------------------------------------------
#define ALD 68   // attn smem row stride (words); 68 % 32 == 4

__global__ void __launch_bounds__(256) attn_mma_kernel()
{
    extern __shared__ float sm[];
    float* Qs = sm;                    // [128][68]
    float* Ks = Qs + 128 * ALD;        // [64][68]  [key][d]
    float* Vt = Ks + 64 * ALD;         // [64][68]  [d][key]
    float* Ps = Vt + 64 * ALD;         // [128][68] per-warp-private rows

    const uint32_t* Qsu = (const uint32_t*)Qs;
    const uint32_t* Ksu = (const uint32_t*)Ks;
    const uint32_t* Vtu = (const uint32_t*)Vt;
    const uint32_t* Psu = (const uint32_t*)Ps;

    const int tid  = threadIdx.x;
    const int lane = tid & 31;
    const int w    = tid >> 5;
    const int g    = lane >> 2;
    const int tg   = lane & 3;

    const int bh = blockIdx.y;
    const int m0 = blockIdx.x * 128;

    const float* qp = g_q + (size_t)bh * Tv * Dv;
    const float* kp = g_k + (size_t)bh * Tv * Dv;
    const float* vp = g_v + (size_t)bh * Tv * Dv;

    // Load Q tile (128x64), scale by 1/sqrt(D) and round to tf32
    {
        const int r  = tid >> 1;
        const int c0 = (tid & 1) * 32;
        #pragma unroll
        for (int j = 0; j < 8; j++) {
            float4 v = *(const float4*)(qp + (size_t)(m0 + r) * Dv + c0 + j * 4);
            v.x = rna_tf32(v.x * 0.125f);
            v.y = rna_tf32(v.y * 0.125f);
            v.z = rna_tf32(v.z * 0.125f);
            v.w = rna_tf32(v.w * 0.125f);
            *(float4*)&Qs[r * ALD + c0 + j * 4] = v;
        }
    }

    const int rbase = 16 * w + g;      // this thread's first S/O row (local)

    float m_i[2] = {-1e30f, -1e30f};
    float l_i[2] = {0.f, 0.f};
    float o[8][4];
    #pragma unroll
    for (int nt = 0; nt < 8; nt++)
        #pragma unroll
        for (int e = 0; e < 4; e++) o[nt][e] = 0.f;

    const int nkt = m0 / 64 + 2;
    for (int kt = 0; kt < nkt; kt++) {
        const int j0 = kt * 64;
        __syncthreads();   // previous iter done reading Ks/Vt (first: Q written)

        // Load K -> Ks[key][d], V -> Vt[d][key] (transposed), tf32-rounded
        {
            const int r  = tid >> 2;
            const int c0 = (tid & 3) * 16;
            #pragma unroll
            for (int j = 0; j < 4; j++) {
                float4 kv = *(const float4*)(kp + (size_t)(j0 + r) * Dv + c0 + j * 4);
                kv.x = rna_tf32(kv.x); kv.y = rna_tf32(kv.y);
                kv.z = rna_tf32(kv.z); kv.w = rna_tf32(kv.w);
                *(float4*)&Ks[r * ALD + c0 + j * 4] = kv;
                float4 vv = *(const float4*)(vp + (size_t)(j0 + r) * Dv + c0 + j * 4);
                Vt[(c0 + j * 4 + 0) * ALD + r] = rna_tf32(vv.x);
                Vt[(c0 + j * 4 + 1) * ALD + r] = rna_tf32(vv.y);
                Vt[(c0 + j * 4 + 2) * ALD + r] = rna_tf32(vv.z);
                Vt[(c0 + j * 4 + 3) * ALD + r] = rna_tf32(vv.w);
            }
        }
        __syncthreads();   // tiles ready

        // ---- S = Q @ K^T (16 rows x 64 keys per warp) ----
        float s[8][4];
        #pragma unroll
        for (int nt = 0; nt < 8; nt++)
            #pragma unroll
            for (int e = 0; e < 4; e++) s[nt][e] = 0.f;

        #pragma unroll
        for (int ks = 0; ks < 8; ks++) {
            const int kk = ks * 8 + tg;
            uint32_t a[4];
            a[0] = Qsu[rbase * ALD + kk];
            a[1] = Qsu[(rbase + 8) * ALD + kk];
            a[2] = Qsu[rbase * ALD + kk + 4];
            a[3] = Qsu[(rbase + 8) * ALD + kk + 4];
            #pragma unroll
            for (int nt = 0; nt < 8; nt++) {
                uint32_t b[2];
                b[0] = Ksu[(nt * 8 + g) * ALD + kk];
                b[1] = Ksu[(nt * 8 + g) * ALD + kk + 4];
                mma16n8k8(s[nt], a, b);
            }
        }

        // ---- causal mask (only near the diagonal) ----
        if (j0 + 63 > m0 + 16 * w) {
            #pragma unroll
            for (int nt = 0; nt < 8; nt++)
                #pragma unroll
                for (int e = 0; e < 4; e++) {
                    const int row = m0 + rbase + (e >> 1) * 8;
                    const int key = j0 + nt * 8 + 2 * tg + (e & 1);
                    if (key > row) s[nt][e] = -1e30f;
                }
        }

        // ---- online softmax (rows rbase, rbase+8) ----
        #pragma unroll
        for (int r2 = 0; r2 < 2; r2++) {
            float mx = -1e30f;
            #pragma unroll
            for (int nt = 0; nt < 8; nt++)
                mx = fmaxf(mx, fmaxf(s[nt][r2 * 2], s[nt][r2 * 2 + 1]));
            mx = fmaxf(mx, __shfl_xor_sync(0xffffffffu, mx, 1));
            mx = fmaxf(mx, __shfl_xor_sync(0xffffffffu, mx, 2));
            const float mn = fmaxf(m_i[r2], mx);
            const float corr = __expf(m_i[r2] - mn);
            m_i[r2] = mn;
            float rs = 0.f;
            #pragma unroll
            for (int nt = 0; nt < 8; nt++) {
                float p0 = __expf(s[nt][r2 * 2]     - mn);
                float p1 = __expf(s[nt][r2 * 2 + 1] - mn);
                s[nt][r2 * 2]     = p0;
                s[nt][r2 * 2 + 1] = p1;
                rs += p0 + p1;
            }
            rs += __shfl_xor_sync(0xffffffffu, rs, 1);
            rs += __shfl_xor_sync(0xffffffffu, rs, 2);
            l_i[r2] = l_i[r2] * corr + rs;
            #pragma unroll
            for (int nt = 0; nt < 8; nt++) {
                o[nt][r2 * 2]     *= corr;
                o[nt][r2 * 2 + 1] *= corr;
            }
        }

        // ---- stage P (per-warp-private rows; warp-only visibility needed) ----
        #pragma unroll
        for (int nt = 0; nt < 8; nt++) {
            *(float2*)&Ps[rbase * ALD + nt * 8 + 2 * tg] =
                make_float2(rna_tf32(s[nt][0]), rna_tf32(s[nt][1]));
            *(float2*)&Ps[(rbase + 8) * ALD + nt * 8 + 2 * tg] =
                make_float2(rna_tf32(s[nt][2]), rna_tf32(s[nt][3]));
        }
        __syncwarp();

        // ---- O += P @ V ----
        #pragma unroll
        for (int ks = 0; ks < 8; ks++) {
            const int kk = ks * 8 + tg;
            uint32_t a[4];
            a[0] = Psu[rbase * ALD + kk];
            a[1] = Psu[(rbase + 8) * ALD + kk];
            a[2] = Psu[rbase * ALD + kk + 4];
            a[3] = Psu[(rbase + 8) * ALD + kk + 4];
            #pragma unroll
            for (int nt = 0; nt < 8; nt++) {
                uint32_t b[2];
                b[0] = Vtu[(nt * 8 + g) * ALD + kk];
                b[1] = Vtu[(nt * 8 + g) * ALD + kk + 4];
                mma16n8k8(o[nt], a, b);
            }
        }
        __syncwarp();   // P reads done before next iter overwrites (warp-private)
    }

    // ---- normalize and write to g_y [B,T,C] ----
    const int b_ = bh >> 4;
    const int head = bh & 15;
    #pragma unroll
    for (int r2 = 0; r2 < 2; r2++) {
        const float inv = 1.f / l_i[r2];
        const int row = m0 + rbase + r2 * 8;
        #pragma unroll
        for (int nt = 0; nt < 8; nt++) {
            float2 v;
            v.x = o[nt][r2 * 2]     * inv;
            v.y = o[nt][r2 * 2 + 1] * inv;
            *(float2*)&g_y[((size_t)(b_ * Tv + row)) * Cv + head * 64 + nt * 8 + 2 * tg] = v;
        }
    }
}

// ---------------------------------------------------------------------------
extern "C" void kernel_launch(void* const* d_in, const int* in_sizes, int n_in,
                              void* d_out, int out_size)
{
    const float* x     = (const float*)d_in[0];
    const float* W_qkv = (const float*)d_in[1];
    const float* b_qkv = (const float*)d_in[2];
    const float* W_out = (const float*)d_in[3];
    const float* b_out = (const float*)d_in[4];
    float* out = (float*)d_out;

    float* wqT; cudaGetSymbolAddress((void**)&wqT, g_wqkvT);
    float* woT; cudaGetSymbolAddress((void**)&woT, g_woutT);

    const int ATTN_SMEM = (128 + 64 + 64 + 128) * ALD * 4;  // 104448 B
    cudaFuncSetAttribute(attn_mma_kernel,
                         cudaFuncAttributeMaxDynamicSharedMemorySize, ATTN_SMEM);

    transpose_kernel<<<dim3(3 * Cv / 32, Cv / 32), dim3(32, 8)>>>(W_qkv, wqT, Cv, 3 * Cv);
    transpose_kernel<<<dim3(Cv / 32, Cv / 32), dim3(32, 8)>>>(W_out, woT, Cv, Cv);

    // 1) QKV projection (tf32 warp MMA) with head scatter
    gemm_mma<0><<<dim3(3 * Cv / 128, Mrows / 128), 256>>>(x, wqT, b_qkv, nullptr);

    // 2) causal flash attention (tf32 warp MMA)
    attn_mma_kernel<<<dim3(Tv / 128, Bv * Hv), 256, ATTN_SMEM>>>();

    // 3) output projection (tf32 warp MMA)
    gemm_mma<1><<<dim3(Cv / 128, Mrows / 128), 256>>>(nullptr, woT, b_out, out);
}

// round 5
// speedup vs baseline: 3.3954x; 1.1315x over previous
#include <cuda_runtime.h>
#include <math.h>
#include <stdint.h>

#define Bv 4
#define Tv 2048
#define Cv 1024
#define Hv 16
#define Dv 64
#define Mrows (Bv*Tv)   // 8192

// ---------------- scratch (device globals; allocation-free) ----------------
__device__ float g_q[Bv*Hv*Tv*Dv];    // [B,H,T,D]
__device__ float g_k[Bv*Hv*Tv*Dv];
__device__ float g_v[Bv*Hv*Tv*Dv];
__device__ float g_y[Bv*Tv*Cv];       // attention output [B,T,C]

__device__ __forceinline__ float rna_tf32(float x) {
    uint32_t u;
    asm("cvt.rna.tf32.f32 %0, %1;" : "=r"(u) : "f"(x));
    return __uint_as_float(u);
}

// m16n8k8 tf32 warp MMA (baseline PTX feature, validated)
__device__ __forceinline__ void mma16n8k8(float* c, const uint32_t* a, const uint32_t* b) {
    asm volatile(
        "mma.sync.aligned.m16n8k8.row.col.f32.tf32.tf32.f32 "
        "{%0,%1,%2,%3}, {%4,%5,%6,%7}, {%8,%9}, {%0,%1,%2,%3};"
        : "+f"(c[0]), "+f"(c[1]), "+f"(c[2]), "+f"(c[3])
        : "r"(a[0]), "r"(a[1]), "r"(a[2]), "r"(a[3]), "r"(b[0]), "r"(b[1]));
}

// ---------------------------------------------------------------------------
// tf32 warp-MMA GEMM: C[M,N] = A[M,1024] @ W[1024,N](+bias), W read directly
// (no pre-transpose). CTA 128x128, BK=32, 256 threads, warp tile 64x32.
// A smem: [128][36] (m-major). W smem: [32][136] (k-major; 136%32==8 ->
// b-frag banks 8*tg+g, conflict-free).
// MODE 0: scatter into g_q/g_k/g_v.  MODE 1: out[row*1024+col].
// ---------------------------------------------------------------------------
#define BK 32
#define LDW 36
#define LDB 136

template<int MODE>
__global__ void __launch_bounds__(256) gemm_mma(
    const float* __restrict__ A_in, const float* __restrict__ W,
    const float* __restrict__ bias, float* __restrict__ out, int ldw)
{
    __shared__ float As[128 * LDW];
    __shared__ float Bs[BK * LDB];

    const float* A = (MODE == 1) ? g_y : A_in;

    const int tid  = threadIdx.x;
    const int lane = tid & 31;
    const int wid  = tid >> 5;
    const int wm   = (wid & 1) * 64;
    const int wn   = (wid >> 1) * 32;
    const int g    = lane >> 2;
    const int tg   = lane & 3;

    const int row0 = blockIdx.y * 128;
    const int col0 = blockIdx.x * 128;
    const float* Ab = A + (size_t)row0 * Cv;
    const float* Wb = W + col0;

    // A granules: f = i*256+tid -> r=f>>3, kc=(f&7)*4
    const int ar = tid >> 3;
    const int ac = (tid & 7) << 2;
    // B granules: f = i*256+tid -> r=f>>5, c4=f&31
    const int br = tid >> 5;
    const int bc = (tid & 31) << 2;

    float c[4][4][4];
    #pragma unroll
    for (int mt = 0; mt < 4; mt++)
        #pragma unroll
        for (int nt = 0; nt < 4; nt++)
            #pragma unroll
            for (int i = 0; i < 4; i++) c[mt][nt][i] = 0.f;

    float4 pa[4], pb[4];
    #pragma unroll
    for (int i = 0; i < 4; i++) {
        pa[i] = *(const float4*)(Ab + (size_t)(ar + i * 32) * Cv + ac);
        pb[i] = *(const float4*)(Wb + (size_t)(br + i * 8) * ldw + bc);
    }

    const uint32_t* Asu = (const uint32_t*)As;
    const uint32_t* Bsu = (const uint32_t*)Bs;

    for (int ch = 0; ch < Cv / BK; ch++) {
        #pragma unroll
        for (int i = 0; i < 4; i++) {
            float4 va = pa[i], vb = pb[i];
            va.x = rna_tf32(va.x); va.y = rna_tf32(va.y);
            va.z = rna_tf32(va.z); va.w = rna_tf32(va.w);
            vb.x = rna_tf32(vb.x); vb.y = rna_tf32(vb.y);
            vb.z = rna_tf32(vb.z); vb.w = rna_tf32(vb.w);
            *(float4*)&As[(ar + i * 32) * LDW + ac] = va;
            *(float4*)&Bs[(br + i * 8) * LDB + bc] = vb;
        }
        __syncthreads();

        if (ch + 1 < Cv / BK) {
            const float* gA = Ab + (ch + 1) * BK;
            const float* gW = Wb + (size_t)(ch + 1) * BK * ldw;
            #pragma unroll
            for (int i = 0; i < 4; i++) {
                pa[i] = *(const float4*)(gA + (size_t)(ar + i * 32) * Cv + ac);
                pb[i] = *(const float4*)(gW + (size_t)(br + i * 8) * ldw + bc);
            }
        }

        #pragma unroll
        for (int ks = 0; ks < 4; ks++) {
            const int kk = ks * 8 + tg;
            uint32_t a[4][4];
            #pragma unroll
            for (int mt = 0; mt < 4; mt++) {
                const int r = wm + mt * 16 + g;
                a[mt][0] = Asu[r * LDW + kk];
                a[mt][1] = Asu[(r + 8) * LDW + kk];
                a[mt][2] = Asu[r * LDW + kk + 4];
                a[mt][3] = Asu[(r + 8) * LDW + kk + 4];
            }
            uint32_t b[4][2];
            #pragma unroll
            for (int nt = 0; nt < 4; nt++) {
                const int n = wn + nt * 8 + g;
                b[nt][0] = Bsu[kk * LDB + n];
                b[nt][1] = Bsu[(kk + 4) * LDB + n];
            }
            #pragma unroll
            for (int mt = 0; mt < 4; mt++)
                #pragma unroll
                for (int nt = 0; nt < 4; nt++)
                    mma16n8k8(c[mt][nt], a[mt], b[nt]);
        }
        __syncthreads();
    }

    #pragma unroll
    for (int mt = 0; mt < 4; mt++) {
        #pragma unroll
        for (int r2 = 0; r2 < 2; r2++) {
            const int row = row0 + wm + mt * 16 + g + r2 * 8;
            const int b_ = row >> 11, t_ = row & 2047;
            #pragma unroll
            for (int nt = 0; nt < 4; nt++) {
                const int col = col0 + wn + nt * 8 + tg * 2;
                float2 v;
                v.x = c[mt][nt][r2 * 2 + 0] + __ldg(bias + col + 0);
                v.y = c[mt][nt][r2 * 2 + 1] + __ldg(bias + col + 1);
                if (MODE == 0) {
                    const int which = col >> 10;
                    const int cc = col & 1023;
                    const int h = cc >> 6, d = cc & 63;
                    float* dst = (which == 0) ? g_q : (which == 1) ? g_k : g_v;
                    *(float2*)&dst[((size_t)((b_ * Hv + h) * Tv + t_)) * Dv + d] = v;
                } else {
                    *(float2*)&out[(size_t)row * Cv + col] = v;
                }
            }
        }
    }
}

// ---------------------------------------------------------------------------
// Flash attention v2 on mma.sync tf32.
// CTA: 128 q-rows, 4 warps x 32 rows, 64 keys/iter.
// V kept untransposed [key][d] with stride 72 (72%32==8 -> b-frag reads
// conflict-free). Q/K/P stride 68 (4g+tg). Per-warp-private P rows.
// ---------------------------------------------------------------------------
#define ALD 68
#define VLD 72

__global__ void __launch_bounds__(128) attn_mma_kernel()
{
    extern __shared__ float sm[];
    float* Qs = sm;                    // [128][68]
    float* Ks = Qs + 128 * ALD;        // [64][68]  [key][d]
    float* Vs = Ks + 64 * ALD;         // [64][72]  [key][d] (B operand direct)
    float* Ps = Vs + 64 * VLD;         // [128][68] per-warp-private rows

    const uint32_t* Qsu = (const uint32_t*)Qs;
    const uint32_t* Ksu = (const uint32_t*)Ks;
    const uint32_t* Vsu = (const uint32_t*)Vs;
    const uint32_t* Psu = (const uint32_t*)Ps;

    const int tid  = threadIdx.x;
    const int lane = tid & 31;
    const int w    = tid >> 5;         // 0..3
    const int g    = lane >> 2;
    const int tg   = lane & 3;

    const int bh = blockIdx.y;
    const int m0 = blockIdx.x * 128;

    const float* qp = g_q + (size_t)bh * Tv * Dv;
    const float* kp = g_k + (size_t)bh * Tv * Dv;
    const float* vp = g_v + (size_t)bh * Tv * Dv;

    // Load Q tile (128x64), scale by 1/8, round to tf32. f-granule mapping.
    #pragma unroll
    for (int i = 0; i < 16; i++) {
        const int f = i * 128 + tid;
        const int r = f >> 4, c4 = (f & 15) << 2;
        float4 v = *(const float4*)(qp + (size_t)(m0 + r) * Dv + c4);
        v.x = rna_tf32(v.x * 0.125f);
        v.y = rna_tf32(v.y * 0.125f);
        v.z = rna_tf32(v.z * 0.125f);
        v.w = rna_tf32(v.w * 0.125f);
        *(float4*)&Qs[r * ALD + c4] = v;
    }

    // per-thread rows: m0 + 32w + 16rc + g (+8)
    const int wrow = 32 * w;

    float m_i[4] = {-1e30f, -1e30f, -1e30f, -1e30f};
    float l_i[4] = {0.f, 0.f, 0.f, 0.f};
    float o[2][8][4];
    #pragma unroll
    for (int rc = 0; rc < 2; rc++)
        #pragma unroll
        for (int nt = 0; nt < 8; nt++)
            #pragma unroll
            for (int e = 0; e < 4; e++) o[rc][nt][e] = 0.f;

    const int nkt = m0 / 64 + 2;
    for (int kt = 0; kt < nkt; kt++) {
        const int j0 = kt * 64;
        __syncthreads();   // prior iter done reading Ks/Vs (first: Q visible after next)

        // Load K -> Ks[key][d] (stride 68), V -> Vs[key][d] (stride 72)
        #pragma unroll
        for (int i = 0; i < 8; i++) {
            const int f = i * 128 + tid;
            const int r = f >> 4, c4 = (f & 15) << 2;
            float4 kv = *(const float4*)(kp + (size_t)(j0 + r) * Dv + c4);
            kv.x = rna_tf32(kv.x); kv.y = rna_tf32(kv.y);
            kv.z = rna_tf32(kv.z); kv.w = rna_tf32(kv.w);
            *(float4*)&Ks[r * ALD + c4] = kv;
            float4 vv = *(const float4*)(vp + (size_t)(j0 + r) * Dv + c4);
            vv.x = rna_tf32(vv.x); vv.y = rna_tf32(vv.y);
            vv.z = rna_tf32(vv.z); vv.w = rna_tf32(vv.w);
            *(float4*)&Vs[r * VLD + c4] = vv;
        }
        __syncthreads();   // tiles ready

        // ---- S = Q @ K^T : 32 rows x 64 keys per warp ----
        float s[2][8][4];
        #pragma unroll
        for (int rc = 0; rc < 2; rc++)
            #pragma unroll
            for (int nt = 0; nt < 8; nt++)
                #pragma unroll
                for (int e = 0; e < 4; e++) s[rc][nt][e] = 0.f;

        #pragma unroll
        for (int ks = 0; ks < 8; ks++) {
            const int kk = ks * 8 + tg;
            uint32_t a[2][4];
            #pragma unroll
            for (int rc = 0; rc < 2; rc++) {
                const int r = wrow + 16 * rc + g;
                a[rc][0] = Qsu[r * ALD + kk];
                a[rc][1] = Qsu[(r + 8) * ALD + kk];
                a[rc][2] = Qsu[r * ALD + kk + 4];
                a[rc][3] = Qsu[(r + 8) * ALD + kk + 4];
            }
            #pragma unroll
            for (int nt = 0; nt < 8; nt++) {
                uint32_t b[2];
                b[0] = Ksu[(nt * 8 + g) * ALD + kk];
                b[1] = Ksu[(nt * 8 + g) * ALD + kk + 4];
                mma16n8k8(s[0][nt], a[0], b);
                mma16n8k8(s[1][nt], a[1], b);
            }
        }

        // ---- causal mask (tiles near the diagonal only) ----
        if (j0 + 63 > m0 + wrow) {
            #pragma unroll
            for (int rc = 0; rc < 2; rc++)
                #pragma unroll
                for (int nt = 0; nt < 8; nt++)
                    #pragma unroll
                    for (int e = 0; e < 4; e++) {
                        const int row = m0 + wrow + 16 * rc + g + (e >> 1) * 8;
                        const int key = j0 + nt * 8 + 2 * tg + (e & 1);
                        if (key > row) s[rc][nt][e] = -1e30f;
                    }
        }

        // ---- online softmax (4 row stats: rc*2+r2) ----
        #pragma unroll
        for (int rc = 0; rc < 2; rc++) {
            #pragma unroll
            for (int r2 = 0; r2 < 2; r2++) {
                const int si = rc * 2 + r2;
                float mx = -1e30f;
                #pragma unroll
                for (int nt = 0; nt < 8; nt++)
                    mx = fmaxf(mx, fmaxf(s[rc][nt][r2 * 2], s[rc][nt][r2 * 2 + 1]));
                mx = fmaxf(mx, __shfl_xor_sync(0xffffffffu, mx, 1));
                mx = fmaxf(mx, __shfl_xor_sync(0xffffffffu, mx, 2));
                const float mn = fmaxf(m_i[si], mx);
                const float corr = __expf(m_i[si] - mn);
                m_i[si] = mn;
                float rs = 0.f;
                #pragma unroll
                for (int nt = 0; nt < 8; nt++) {
                    float p0 = __expf(s[rc][nt][r2 * 2]     - mn);
                    float p1 = __expf(s[rc][nt][r2 * 2 + 1] - mn);
                    s[rc][nt][r2 * 2]     = p0;
                    s[rc][nt][r2 * 2 + 1] = p1;
                    rs += p0 + p1;
                }
                rs += __shfl_xor_sync(0xffffffffu, rs, 1);
                rs += __shfl_xor_sync(0xffffffffu, rs, 2);
                l_i[si] = l_i[si] * corr + rs;
                #pragma unroll
                for (int nt = 0; nt < 8; nt++) {
                    o[rc][nt][r2 * 2]     *= corr;
                    o[rc][nt][r2 * 2 + 1] *= corr;
                }
            }
        }

        // ---- stage P (rows exclusively owned by this warp) ----
        #pragma unroll
        for (int rc = 0; rc < 2; rc++) {
            const int r = wrow + 16 * rc + g;
            #pragma unroll
            for (int nt = 0; nt < 8; nt++) {
                *(float2*)&Ps[r * ALD + nt * 8 + 2 * tg] =
                    make_float2(rna_tf32(s[rc][nt][0]), rna_tf32(s[rc][nt][1]));
                *(float2*)&Ps[(r + 8) * ALD + nt * 8 + 2 * tg] =
                    make_float2(rna_tf32(s[rc][nt][2]), rna_tf32(s[rc][nt][3]));
            }
        }
        __syncwarp();

        // ---- O += P @ V (V read untransposed as col-major B) ----
        #pragma unroll
        for (int ks = 0; ks < 8; ks++) {
            const int kk = ks * 8 + tg;
            uint32_t a[2][4];
            #pragma unroll
            for (int rc = 0; rc < 2; rc++) {
                const int r = wrow + 16 * rc + g;
                a[rc][0] = Psu[r * ALD + kk];
                a[rc][1] = Psu[(r + 8) * ALD + kk];
                a[rc][2] = Psu[r * ALD + kk + 4];
                a[rc][3] = Psu[(r + 8) * ALD + kk + 4];
            }
            #pragma unroll
            for (int nt = 0; nt < 8; nt++) {
                uint32_t b[2];
                b[0] = Vsu[kk * VLD + nt * 8 + g];
                b[1] = Vsu[(kk + 4) * VLD + nt * 8 + g];
                mma16n8k8(o[0][nt], a[0], b);
                mma16n8k8(o[1][nt], a[1], b);
            }
        }
        __syncwarp();
    }

    // ---- normalize and write g_y [B,T,C] ----
    const int b_ = bh >> 4;
    const int head = bh & 15;
    #pragma unroll
    for (int rc = 0; rc < 2; rc++) {
        #pragma unroll
        for (int r2 = 0; r2 < 2; r2++) {
            const float inv = 1.f / l_i[rc * 2 + r2];
            const int row = m0 + wrow + 16 * rc + g + r2 * 8;
            #pragma unroll
            for (int nt = 0; nt < 8; nt++) {
                float2 v;
                v.x = o[rc][nt][r2 * 2]     * inv;
                v.y = o[rc][nt][r2 * 2 + 1] * inv;
                *(float2*)&g_y[((size_t)(b_ * Tv + row)) * Cv + head * 64 + nt * 8 + 2 * tg] = v;
            }
        }
    }
}

// ---------------------------------------------------------------------------
extern "C" void kernel_launch(void* const* d_in, const int* in_sizes, int n_in,
                              void* d_out, int out_size)
{
    const float* x     = (const float*)d_in[0];
    const float* W_qkv = (const float*)d_in[1];
    const float* b_qkv = (const float*)d_in[2];
    const float* W_out = (const float*)d_in[3];
    const float* b_out = (const float*)d_in[4];
    float* out = (float*)d_out;

    const int ATTN_SMEM = (128 * ALD + 64 * ALD + 64 * VLD + 128 * ALD) * 4; // 105472
    cudaFuncSetAttribute(attn_mma_kernel,
                         cudaFuncAttributeMaxDynamicSharedMemorySize, ATTN_SMEM);

    // 1) QKV projection (tf32 warp MMA, direct-W) with head scatter
    gemm_mma<0><<<dim3(3 * Cv / 128, Mrows / 128), 256>>>(x, W_qkv, b_qkv, nullptr, 3 * Cv);

    // 2) causal flash attention (tf32 warp MMA, 32-row warp tiles)
    attn_mma_kernel<<<dim3(Tv / 128, Bv * Hv), 128, ATTN_SMEM>>>();

    // 3) output projection (tf32 warp MMA, direct-W)
    gemm_mma<1><<<dim3(Cv / 128, Mrows / 128), 256>>>(nullptr, W_out, b_out, out, Cv);
}

// round 6
// speedup vs baseline: 3.4797x; 1.0248x over previous
#include <cuda_runtime.h>
#include <math.h>
#include <stdint.h>

#define Bv 4
#define Tv 2048
#define Cv 1024
#define Hv 16
#define Dv 64
#define Mrows (Bv*Tv)   // 8192

// ---------------- scratch (device globals; allocation-free) ----------------
__device__ float g_q[Bv*Hv*Tv*Dv];    // [B,H,T,D] (tf32-rounded)
__device__ float g_k[Bv*Hv*Tv*Dv];
__device__ float g_v[Bv*Hv*Tv*Dv];
__device__ float g_y[Bv*Tv*Cv];       // attention output [B,T,C] (tf32-rounded)
__device__ float g_xr[Mrows*Cv];      // x, tf32-rounded
__device__ float g_wq[3*Cv*Cv];       // W_qkv, tf32-rounded (same [K][N] layout)
__device__ float g_wo[Cv*Cv];         // W_out, tf32-rounded

__device__ __forceinline__ float rna_tf32(float x) {
    uint32_t u;
    asm("cvt.rna.tf32.f32 %0, %1;" : "=r"(u) : "f"(x));
    return __uint_as_float(u);
}

__device__ __forceinline__ void mma16n8k8(float* c, const uint32_t* a, const uint32_t* b) {
    asm volatile(
        "mma.sync.aligned.m16n8k8.row.col.f32.tf32.tf32.f32 "
        "{%0,%1,%2,%3}, {%4,%5,%6,%7}, {%8,%9}, {%0,%1,%2,%3};"
        : "+f"(c[0]), "+f"(c[1]), "+f"(c[2]), "+f"(c[3])
        : "r"(a[0]), "r"(a[1]), "r"(a[2]), "r"(a[3]), "r"(b[0]), "r"(b[1]));
}

__device__ __forceinline__ void cp_async16(uint32_t dst, const float* src) {
    asm volatile("cp.async.cg.shared.global [%0], [%1], 16;" :: "r"(dst), "l"(src) : "memory");
}

// ---------------- prep: tf32 rounding pass ----------------
__global__ void round_rna_kernel(const float4* __restrict__ src, float4* __restrict__ dst, int n4) {
    for (int i = blockIdx.x * blockDim.x + threadIdx.x; i < n4; i += gridDim.x * blockDim.x) {
        float4 v = src[i];
        v.x = rna_tf32(v.x); v.y = rna_tf32(v.y);
        v.z = rna_tf32(v.z); v.w = rna_tf32(v.w);
        dst[i] = v;
    }
}

// ---------------------------------------------------------------------------
// tf32 warp-MMA GEMM, cp.async double-buffered, operands pre-rounded.
// C[M,N] = A[M,1024] @ W[1024,N] + bias. CTA 128x128, BK=32, 256 threads,
// warp tile 64x32. A smem [128][36]; W smem [32][136].
// MODE 0: scatter rna-rounded into g_q/g_k/g_v.  MODE 1: out raw fp32.
// ---------------------------------------------------------------------------
#define BK 32
#define LDW 36
#define LDB 136
#define GEMM_SMEM ((2*128*LDW + 2*BK*LDB) * 4)   // 71680 B

template<int MODE>
__global__ void __launch_bounds__(256) gemm_mma(
    const float* __restrict__ A_in, const float* __restrict__ W,
    const float* __restrict__ bias, float* __restrict__ out, int ldw)
{
    extern __shared__ float smg[];
    float* As = smg;                    // [2][128*36]
    float* Bs = smg + 2 * 128 * LDW;    // [2][32*136]

    const float* A = (MODE == 1) ? g_y : A_in;

    const int tid  = threadIdx.x;
    const int lane = tid & 31;
    const int wid  = tid >> 5;
    const int wm   = (wid & 1) * 64;
    const int wn   = (wid >> 1) * 32;
    const int g    = lane >> 2;
    const int tg   = lane & 3;

    const int row0 = blockIdx.y * 128;
    const int col0 = blockIdx.x * 128;
    const float* Ab = A + (size_t)row0 * Cv;
    const float* Wb = W + col0;

    const int ar = tid >> 3;           // A granule row
    const int ac = (tid & 7) << 2;     // A granule k-col
    const int br = tid >> 5;           // B granule k-row
    const int bc = (tid & 31) << 2;    // B granule n-col

    const uint32_t aBase = (uint32_t)__cvta_generic_to_shared(As);
    const uint32_t bBase = (uint32_t)__cvta_generic_to_shared(Bs);

    float c[4][4][4];
    #pragma unroll
    for (int mt = 0; mt < 4; mt++)
        #pragma unroll
        for (int nt = 0; nt < 4; nt++)
            #pragma unroll
            for (int i = 0; i < 4; i++) c[mt][nt][i] = 0.f;

    // issue chunk ch into buffer ch&1
    auto issue = [&](int ch) {
        const int s = ch & 1;
        const float* gA = Ab + ch * BK;
        const float* gW = Wb + (size_t)ch * BK * ldw;
        const uint32_t ab = aBase + (uint32_t)(s * 128 * LDW * 4);
        const uint32_t bb = bBase + (uint32_t)(s * BK * LDB * 4);
        #pragma unroll
        for (int i = 0; i < 4; i++) {
            cp_async16(ab + (uint32_t)(((ar + i * 32) * LDW + ac) * 4),
                       gA + (size_t)(ar + i * 32) * Cv + ac);
            cp_async16(bb + (uint32_t)(((br + i * 8) * LDB + bc) * 4),
                       gW + (size_t)(br + i * 8) * ldw + bc);
        }
        asm volatile("cp.async.commit_group;" ::: "memory");
    };

    issue(0);

    const int NC = Cv / BK;   // 32
    for (int ch = 0; ch < NC; ch++) {
        if (ch + 1 < NC) {
            issue(ch + 1);
            asm volatile("cp.async.wait_group 1;" ::: "memory");
        } else {
            asm volatile("cp.async.wait_group 0;" ::: "memory");
        }
        __syncthreads();

        const int s = ch & 1;
        const uint32_t* Asu = (const uint32_t*)(As + s * 128 * LDW);
        const uint32_t* Bsu = (const uint32_t*)(Bs + s * BK * LDB);

        #pragma unroll
        for (int ks = 0; ks < 4; ks++) {
            const int kk = ks * 8 + tg;
            uint32_t a[4][4];
            #pragma unroll
            for (int mt = 0; mt < 4; mt++) {
                const int r = wm + mt * 16 + g;
                a[mt][0] = Asu[r * LDW + kk];
                a[mt][1] = Asu[(r + 8) * LDW + kk];
                a[mt][2] = Asu[r * LDW + kk + 4];
                a[mt][3] = Asu[(r + 8) * LDW + kk + 4];
            }
            uint32_t b[4][2];
            #pragma unroll
            for (int nt = 0; nt < 4; nt++) {
                const int n = wn + nt * 8 + g;
                b[nt][0] = Bsu[kk * LDB + n];
                b[nt][1] = Bsu[(kk + 4) * LDB + n];
            }
            #pragma unroll
            for (int mt = 0; mt < 4; mt++)
                #pragma unroll
                for (int nt = 0; nt < 4; nt++)
                    mma16n8k8(c[mt][nt], a[mt], b[nt]);
        }
        __syncthreads();   // all warps done with buffer s before it is refilled
    }

    #pragma unroll
    for (int mt = 0; mt < 4; mt++) {
        #pragma unroll
        for (int r2 = 0; r2 < 2; r2++) {
            const int row = row0 + wm + mt * 16 + g + r2 * 8;
            const int b_ = row >> 11, t_ = row & 2047;
            #pragma unroll
            for (int nt = 0; nt < 4; nt++) {
                const int col = col0 + wn + nt * 8 + tg * 2;
                float2 v;
                v.x = c[mt][nt][r2 * 2 + 0] + __ldg(bias + col + 0);
                v.y = c[mt][nt][r2 * 2 + 1] + __ldg(bias + col + 1);
                if (MODE == 0) {
                    v.x = rna_tf32(v.x);      // pre-round q/k/v for attention mma
                    v.y = rna_tf32(v.y);
                    const int which = col >> 10;
                    const int cc = col & 1023;
                    const int h = cc >> 6, d = cc & 63;
                    float* dst = (which == 0) ? g_q : (which == 1) ? g_k : g_v;
                    *(float2*)&dst[((size_t)((b_ * Hv + h) * Tv + t_)) * Dv + d] = v;
                } else {
                    *(float2*)&out[(size_t)row * Cv + col] = v;   // final: full fp32
                }
            }
        }
    }
}

// ---------------------------------------------------------------------------
// Flash attention on mma.sync tf32. CTA: 128 q-rows, 4 warps x 32 rows,
// 64 keys/iter. q/k/v arrive pre-rounded (no cvt on loads).
// V untransposed [key][d] stride 72; Q/K/P stride 68. Per-warp-private P.
// ---------------------------------------------------------------------------
#define ALD 68
#define VLD 72

__global__ void __launch_bounds__(128) attn_mma_kernel()
{
    extern __shared__ float sm[];
    float* Qs = sm;                    // [128][68]
    float* Ks = Qs + 128 * ALD;        // [64][68]
    float* Vs = Ks + 64 * ALD;         // [64][72]
    float* Ps = Vs + 64 * VLD;         // [128][68]

    const uint32_t* Qsu = (const uint32_t*)Qs;
    const uint32_t* Ksu = (const uint32_t*)Ks;
    const uint32_t* Vsu = (const uint32_t*)Vs;
    const uint32_t* Psu = (const uint32_t*)Ps;

    const int tid  = threadIdx.x;
    const int lane = tid & 31;
    const int w    = tid >> 5;
    const int g    = lane >> 2;
    const int tg   = lane & 3;

    const int bh = blockIdx.y;
    const int m0 = blockIdx.x * 128;

    const float* qp = g_q + (size_t)bh * Tv * Dv;
    const float* kp = g_k + (size_t)bh * Tv * Dv;
    const float* vp = g_v + (size_t)bh * Tv * Dv;

    // Load Q tile (128x64); values pre-rounded, 0.125 scale exact.
    #pragma unroll
    for (int i = 0; i < 16; i++) {
        const int f = i * 128 + tid;
        const int r = f >> 4, c4 = (f & 15) << 2;
        float4 v = *(const float4*)(qp + (size_t)(m0 + r) * Dv + c4);
        v.x *= 0.125f; v.y *= 0.125f; v.z *= 0.125f; v.w *= 0.125f;
        *(float4*)&Qs[r * ALD + c4] = v;
    }

    const int wrow = 32 * w;

    float m_i[4] = {-1e30f, -1e30f, -1e30f, -1e30f};
    float l_i[4] = {0.f, 0.f, 0.f, 0.f};
    float o[2][8][4];
    #pragma unroll
    for (int rc = 0; rc < 2; rc++)
        #pragma unroll
        for (int nt = 0; nt < 8; nt++)
            #pragma unroll
            for (int e = 0; e < 4; e++) o[rc][nt][e] = 0.f;

    const int nkt = m0 / 64 + 2;
    for (int kt = 0; kt < nkt; kt++) {
        const int j0 = kt * 64;
        __syncthreads();

        #pragma unroll
        for (int i = 0; i < 8; i++) {
            const int f = i * 128 + tid;
            const int r = f >> 4, c4 = (f & 15) << 2;
            *(float4*)&Ks[r * ALD + c4] =
                *(const float4*)(kp + (size_t)(j0 + r) * Dv + c4);
            *(float4*)&Vs[r * VLD + c4] =
                *(const float4*)(vp + (size_t)(j0 + r) * Dv + c4);
        }
        __syncthreads();

        // ---- S = Q @ K^T ----
        float s[2][8][4];
        #pragma unroll
        for (int rc = 0; rc < 2; rc++)
            #pragma unroll
            for (int nt = 0; nt < 8; nt++)
                #pragma unroll
                for (int e = 0; e < 4; e++) s[rc][nt][e] = 0.f;

        #pragma unroll
        for (int ks = 0; ks < 8; ks++) {
            const int kk = ks * 8 + tg;
            uint32_t a[2][4];
            #pragma unroll
            for (int rc = 0; rc < 2; rc++) {
                const int r = wrow + 16 * rc + g;
                a[rc][0] = Qsu[r * ALD + kk];
                a[rc][1] = Qsu[(r + 8) * ALD + kk];
                a[rc][2] = Qsu[r * ALD + kk + 4];
                a[rc][3] = Qsu[(r + 8) * ALD + kk + 4];
            }
            #pragma unroll
            for (int nt = 0; nt < 8; nt++) {
                uint32_t b[2];
                b[0] = Ksu[(nt * 8 + g) * ALD + kk];
                b[1] = Ksu[(nt * 8 + g) * ALD + kk + 4];
                mma16n8k8(s[0][nt], a[0], b);
                mma16n8k8(s[1][nt], a[1], b);
            }
        }

        // ---- causal mask ----
        if (j0 + 63 > m0 + wrow) {
            #pragma unroll
            for (int rc = 0; rc < 2; rc++)
                #pragma unroll
                for (int nt = 0; nt < 8; nt++)
                    #pragma unroll
                    for (int e = 0; e < 4; e++) {
                        const int row = m0 + wrow + 16 * rc + g + (e >> 1) * 8;
                        const int key = j0 + nt * 8 + 2 * tg + (e & 1);
                        if (key > row) s[rc][nt][e] = -1e30f;
                    }
        }

        // ---- online softmax ----
        #pragma unroll
        for (int rc = 0; rc < 2; rc++) {
            #pragma unroll
            for (int r2 = 0; r2 < 2; r2++) {
                const int si = rc * 2 + r2;
                float mx = -1e30f;
                #pragma unroll
                for (int nt = 0; nt < 8; nt++)
                    mx = fmaxf(mx, fmaxf(s[rc][nt][r2 * 2], s[rc][nt][r2 * 2 + 1]));
                mx = fmaxf(mx, __shfl_xor_sync(0xffffffffu, mx, 1));
                mx = fmaxf(mx, __shfl_xor_sync(0xffffffffu, mx, 2));
                const float mn = fmaxf(m_i[si], mx);
                const float corr = __expf(m_i[si] - mn);
                m_i[si] = mn;
                float rs = 0.f;
                #pragma unroll
                for (int nt = 0; nt < 8; nt++) {
                    float p0 = __expf(s[rc][nt][r2 * 2]     - mn);
                    float p1 = __expf(s[rc][nt][r2 * 2 + 1] - mn);
                    s[rc][nt][r2 * 2]     = p0;
                    s[rc][nt][r2 * 2 + 1] = p1;
                    rs += p0 + p1;
                }
                rs += __shfl_xor_sync(0xffffffffu, rs, 1);
                rs += __shfl_xor_sync(0xffffffffu, rs, 2);
                l_i[si] = l_i[si] * corr + rs;
                #pragma unroll
                for (int nt = 0; nt < 8; nt++) {
                    o[rc][nt][r2 * 2]     *= corr;
                    o[rc][nt][r2 * 2 + 1] *= corr;
                }
            }
        }

        // ---- stage P (warp-private rows) ----
        #pragma unroll
        for (int rc = 0; rc < 2; rc++) {
            const int r = wrow + 16 * rc + g;
            #pragma unroll
            for (int nt = 0; nt < 8; nt++) {
                *(float2*)&Ps[r * ALD + nt * 8 + 2 * tg] =
                    make_float2(rna_tf32(s[rc][nt][0]), rna_tf32(s[rc][nt][1]));
                *(float2*)&Ps[(r + 8) * ALD + nt * 8 + 2 * tg] =
                    make_float2(rna_tf32(s[rc][nt][2]), rna_tf32(s[rc][nt][3]));
            }
        }
        __syncwarp();

        // ---- O += P @ V ----
        #pragma unroll
        for (int ks = 0; ks < 8; ks++) {
            const int kk = ks * 8 + tg;
            uint32_t a[2][4];
            #pragma unroll
            for (int rc = 0; rc < 2; rc++) {
                const int r = wrow + 16 * rc + g;
                a[rc][0] = Psu[r * ALD + kk];
                a[rc][1] = Psu[(r + 8) * ALD + kk];
                a[rc][2] = Psu[r * ALD + kk + 4];
                a[rc][3] = Psu[(r + 8) * ALD + kk + 4];
            }
            #pragma unroll
            for (int nt = 0; nt < 8; nt++) {
                uint32_t b[2];
                b[0] = Vsu[kk * VLD + nt * 8 + g];
                b[1] = Vsu[(kk + 4) * VLD + nt * 8 + g];
                mma16n8k8(o[0][nt], a[0], b);
                mma16n8k8(o[1][nt], a[1], b);
            }
        }
        __syncwarp();
    }

    // ---- normalize, round to tf32 (consumed by gemm<1>), write g_y ----
    const int b_ = bh >> 4;
    const int head = bh & 15;
    #pragma unroll
    for (int rc = 0; rc < 2; rc++) {
        #pragma unroll
        for (int r2 = 0; r2 < 2; r2++) {
            const float inv = 1.f / l_i[rc * 2 + r2];
            const int row = m0 + wrow + 16 * rc + g + r2 * 8;
            #pragma unroll
            for (int nt = 0; nt < 8; nt++) {
                float2 v;
                v.x = rna_tf32(o[rc][nt][r2 * 2]     * inv);
                v.y = rna_tf32(o[rc][nt][r2 * 2 + 1] * inv);
                *(float2*)&g_y[((size_t)(b_ * Tv + row)) * Cv + head * 64 + nt * 8 + 2 * tg] = v;
            }
        }
    }
}

// ---------------------------------------------------------------------------
extern "C" void kernel_launch(void* const* d_in, const int* in_sizes, int n_in,
                              void* d_out, int out_size)
{
    const float* x     = (const float*)d_in[0];
    const float* W_qkv = (const float*)d_in[1];
    const float* b_qkv = (const float*)d_in[2];
    const float* W_out = (const float*)d_in[3];
    const float* b_out = (const float*)d_in[4];
    float* out = (float*)d_out;

    float* xr; cudaGetSymbolAddress((void**)&xr, g_xr);
    float* wq; cudaGetSymbolAddress((void**)&wq, g_wq);
    float* wo; cudaGetSymbolAddress((void**)&wo, g_wo);

    const int ATTN_SMEM = (128 * ALD + 64 * ALD + 64 * VLD + 128 * ALD) * 4; // 105472
    cudaFuncSetAttribute(attn_mma_kernel,
                         cudaFuncAttributeMaxDynamicSharedMemorySize, ATTN_SMEM);
    cudaFuncSetAttribute(gemm_mma<0>,
                         cudaFuncAttributeMaxDynamicSharedMemorySize, GEMM_SMEM);
    cudaFuncSetAttribute(gemm_mma<1>,
                         cudaFuncAttributeMaxDynamicSharedMemorySize, GEMM_SMEM);

    // prep: tf32-round all GEMM operands once
    round_rna_kernel<<<2048, 256>>>((const float4*)x, (float4*)xr, Mrows * Cv / 4);
    round_rna_kernel<<<1024, 256>>>((const float4*)W_qkv, (float4*)wq, 3 * Cv * Cv / 4);
    round_rna_kernel<<<512, 256>>>((const float4*)W_out, (float4*)wo, Cv * Cv / 4);

    // 1) QKV projection (cp.async tf32 warp MMA) with rounded head scatter
    gemm_mma<0><<<dim3(3 * Cv / 128, Mrows / 128), 256, GEMM_SMEM>>>(xr, wq, b_qkv, nullptr, 3 * Cv);

    // 2) causal flash attention (tf32 warp MMA)
    attn_mma_kernel<<<dim3(Tv / 128, Bv * Hv), 128, ATTN_SMEM>>>();

    // 3) output projection (cp.async tf32 warp MMA)
    gemm_mma<1><<<dim3(Cv / 128, Mrows / 128), 256, GEMM_SMEM>>>(nullptr, wo, b_out, out, Cv);
}

// round 7
// speedup vs baseline: 3.5920x; 1.0323x over previous
#include <cuda_runtime.h>
#include <math.h>
#include <stdint.h>

#define Bv 4
#define Tv 2048
#define Cv 1024
#define Hv 16
#define Dv 64
#define Mrows (Bv*Tv)   // 8192

// ---------------- scratch (device globals; allocation-free) ----------------
__device__ float g_q[Bv*Hv*Tv*Dv];    // [B,H,T,D] (tf32-rounded)
__device__ float g_k[Bv*Hv*Tv*Dv];
__device__ float g_v[Bv*Hv*Tv*Dv];
__device__ float g_y[Bv*Tv*Cv];       // attention output [B,T,C] (tf32-rounded)
__device__ float g_xr[Mrows*Cv];      // x, tf32-rounded
__device__ float g_wq[3*Cv*Cv];       // W_qkv, tf32-rounded
__device__ float g_wo[Cv*Cv];         // W_out, tf32-rounded

__device__ __forceinline__ float rna_tf32(float x) {
    uint32_t u;
    asm("cvt.rna.tf32.f32 %0, %1;" : "=r"(u) : "f"(x));
    return __uint_as_float(u);
}

__device__ __forceinline__ void mma16n8k8(float* c, const uint32_t* a, const uint32_t* b) {
    asm volatile(
        "mma.sync.aligned.m16n8k8.row.col.f32.tf32.tf32.f32 "
        "{%0,%1,%2,%3}, {%4,%5,%6,%7}, {%8,%9}, {%0,%1,%2,%3};"
        : "+f"(c[0]), "+f"(c[1]), "+f"(c[2]), "+f"(c[3])
        : "r"(a[0]), "r"(a[1]), "r"(a[2]), "r"(a[3]), "r"(b[0]), "r"(b[1]));
}

__device__ __forceinline__ void cp_async16(uint32_t dst, const float* src) {
    asm volatile("cp.async.cg.shared.global [%0], [%1], 16;" :: "r"(dst), "l"(src) : "memory");
}

// ---------------- prep: tf32 rounding pass ----------------
__global__ void round_rna_kernel(const float4* __restrict__ src, float4* __restrict__ dst, int n4) {
    for (int i = blockIdx.x * blockDim.x + threadIdx.x; i < n4; i += gridDim.x * blockDim.x) {
        float4 v = src[i];
        v.x = rna_tf32(v.x); v.y = rna_tf32(v.y);
        v.z = rna_tf32(v.z); v.w = rna_tf32(v.w);
        dst[i] = v;
    }
}

// ---------------------------------------------------------------------------
// tf32 warp-MMA GEMM, 3-stage cp.async pipeline, ONE barrier per chunk.
// C[M,N] = A[M,1024] @ W[1024,N] + bias. CTA 128x128, BK=32, 256 threads,
// warp tile 64x32. A smem [128][36]; W smem [32][136].
// ---------------------------------------------------------------------------
#define BK 32
#define LDW 36
#define LDB 136
#define NSTG 3
#define GEMM_SMEM ((NSTG*128*LDW + NSTG*BK*LDB) * 4)   // 107520 B

template<int MODE>
__global__ void __launch_bounds__(256) gemm_mma(
    const float* __restrict__ A_in, const float* __restrict__ W,
    const float* __restrict__ bias, float* __restrict__ out, int ldw)
{
    extern __shared__ float smg[];
    float* As = smg;                       // [NSTG][128*36]
    float* Bs = smg + NSTG * 128 * LDW;    // [NSTG][32*136]

    const float* A = (MODE == 1) ? g_y : A_in;

    const int tid  = threadIdx.x;
    const int lane = tid & 31;
    const int wid  = tid >> 5;
    const int wm   = (wid & 1) * 64;
    const int wn   = (wid >> 1) * 32;
    const int g    = lane >> 2;
    const int tg   = lane & 3;

    const int row0 = blockIdx.y * 128;
    const int col0 = blockIdx.x * 128;
    const float* Ab = A + (size_t)row0 * Cv;
    const float* Wb = W + col0;

    const int ar = tid >> 3;
    const int ac = (tid & 7) << 2;
    const int br = tid >> 5;
    const int bc = (tid & 31) << 2;

    const uint32_t aBase = (uint32_t)__cvta_generic_to_shared(As);
    const uint32_t bBase = (uint32_t)__cvta_generic_to_shared(Bs);

    float c[4][4][4];
    #pragma unroll
    for (int mt = 0; mt < 4; mt++)
        #pragma unroll
        for (int nt = 0; nt < 4; nt++)
            #pragma unroll
            for (int i = 0; i < 4; i++) c[mt][nt][i] = 0.f;

    const int NC = Cv / BK;   // 32

    auto issue = [&](int ch) {
        if (ch < NC) {
            const int s = ch % NSTG;
            const float* gA = Ab + ch * BK;
            const float* gW = Wb + (size_t)ch * BK * ldw;
            const uint32_t ab = aBase + (uint32_t)(s * 128 * LDW * 4);
            const uint32_t bb = bBase + (uint32_t)(s * BK * LDB * 4);
            #pragma unroll
            for (int i = 0; i < 4; i++) {
                cp_async16(ab + (uint32_t)(((ar + i * 32) * LDW + ac) * 4),
                           gA + (size_t)(ar + i * 32) * Cv + ac);
                cp_async16(bb + (uint32_t)(((br + i * 8) * LDB + bc) * 4),
                           gW + (size_t)(br + i * 8) * ldw + bc);
            }
        }
        asm volatile("cp.async.commit_group;" ::: "memory");
    };

    issue(0);
    issue(1);

    for (int ch = 0; ch < NC; ch++) {
        asm volatile("cp.async.wait_group 1;" ::: "memory");
        __syncthreads();          // all warps done with stage (ch-1)%NSTG; chunk ch visible
        issue(ch + 2);            // refill the stage freed at iter ch-1

        const int s = ch % NSTG;
        const uint32_t* Asu = (const uint32_t*)(As + s * 128 * LDW);
        const uint32_t* Bsu = (const uint32_t*)(Bs + s * BK * LDB);

        #pragma unroll
        for (int ks = 0; ks < 4; ks++) {
            const int kk = ks * 8 + tg;
            uint32_t a[4][4];
            #pragma unroll
            for (int mt = 0; mt < 4; mt++) {
                const int r = wm + mt * 16 + g;
                a[mt][0] = Asu[r * LDW + kk];
                a[mt][1] = Asu[(r + 8) * LDW + kk];
                a[mt][2] = Asu[r * LDW + kk + 4];
                a[mt][3] = Asu[(r + 8) * LDW + kk + 4];
            }
            uint32_t b[4][2];
            #pragma unroll
            for (int nt = 0; nt < 4; nt++) {
                const int n = wn + nt * 8 + g;
                b[nt][0] = Bsu[kk * LDB + n];
                b[nt][1] = Bsu[(kk + 4) * LDB + n];
            }
            #pragma unroll
            for (int mt = 0; mt < 4; mt++)
                #pragma unroll
                for (int nt = 0; nt < 4; nt++)
                    mma16n8k8(c[mt][nt], a[mt], b[nt]);
        }
    }

    #pragma unroll
    for (int mt = 0; mt < 4; mt++) {
        #pragma unroll
        for (int r2 = 0; r2 < 2; r2++) {
            const int row = row0 + wm + mt * 16 + g + r2 * 8;
            const int b_ = row >> 11, t_ = row & 2047;
            #pragma unroll
            for (int nt = 0; nt < 4; nt++) {
                const int col = col0 + wn + nt * 8 + tg * 2;
                float2 v;
                v.x = c[mt][nt][r2 * 2 + 0] + __ldg(bias + col + 0);
                v.y = c[mt][nt][r2 * 2 + 1] + __ldg(bias + col + 1);
                if (MODE == 0) {
                    v.x = rna_tf32(v.x);
                    v.y = rna_tf32(v.y);
                    const int which = col >> 10;
                    const int cc = col & 1023;
                    const int h = cc >> 6, d = cc & 63;
                    float* dst = (which == 0) ? g_q : (which == 1) ? g_k : g_v;
                    *(float2*)&dst[((size_t)((b_ * Hv + h) * Tv + t_)) * Dv + d] = v;
                } else {
                    *(float2*)&out[(size_t)row * Cv + col] = v;
                }
            }
        }
    }
}

// ---------------------------------------------------------------------------
// Flash attention on mma.sync tf32.
// CTA: 128 q-rows, 4 warps x 32 rows, 64 keys/iter.
// - K/V double-buffered via cp.async, ONE barrier per k-tile.
// - Q fragments hoisted to registers once; Q smem reused as P staging.
// Smem: QP[128][68] + 2 x (K[64][68] + V[64][72]) = 104 KB -> 2 CTAs/SM.
// ---------------------------------------------------------------------------
#define ALD 68
#define VLD 72
#define KVSTG (64*ALD + 64*VLD)   // floats per K/V stage
#define ATTN_SMEM ((128*ALD + 2*KVSTG) * 4)   // 106496 B

__global__ void __launch_bounds__(128) attn_mma_kernel()
{
    extern __shared__ float sm[];
    float* QP = sm;                    // [128][68]: Q during prologue, P after
    float* KV = sm + 128 * ALD;        // 2 stages

    const uint32_t kvBase = (uint32_t)__cvta_generic_to_shared(KV);

    const int tid  = threadIdx.x;
    const int lane = tid & 31;
    const int w    = tid >> 5;
    const int g    = lane >> 2;
    const int tg   = lane & 3;

    const int bh = blockIdx.y;
    const int m0 = blockIdx.x * 128;

    const float* qp = g_q + (size_t)bh * Tv * Dv;
    const float* kp = g_k + (size_t)bh * Tv * Dv;
    const float* vp = g_v + (size_t)bh * Tv * Dv;

    auto issue_kv = [&](int kt) {
        const int s = kt & 1;
        const float* kpt = kp + (size_t)(kt * 64) * Dv;
        const float* vpt = vp + (size_t)(kt * 64) * Dv;
        const uint32_t kb = kvBase + (uint32_t)(s * KVSTG * 4);
        const uint32_t vb = kb + (uint32_t)(64 * ALD * 4);
        #pragma unroll
        for (int i = 0; i < 8; i++) {
            const int f = i * 128 + tid;
            const int r = f >> 4, c4 = (f & 15) << 2;
            cp_async16(kb + (uint32_t)((r * ALD + c4) * 4), kpt + r * Dv + c4);
            cp_async16(vb + (uint32_t)((r * VLD + c4) * 4), vpt + r * Dv + c4);
        }
        asm volatile("cp.async.commit_group;" ::: "memory");
    };

    issue_kv(0);   // start K/V stream before Q staging

    // Load Q tile (128x64) into QP, scaled by 1/8 (exact; values pre-rounded)
    #pragma unroll
    for (int i = 0; i < 16; i++) {
        const int f = i * 128 + tid;
        const int r = f >> 4, c4 = (f & 15) << 2;
        float4 v = *(const float4*)(qp + (size_t)(m0 + r) * Dv + c4);
        v.x *= 0.125f; v.y *= 0.125f; v.z *= 0.125f; v.w *= 0.125f;
        *(float4*)&QP[r * ALD + c4] = v;
    }
    __syncthreads();

    // Hoist Q fragments to registers (64 regs); QP becomes P staging after this.
    const int wrow = 32 * w;
    const uint32_t* QPu = (const uint32_t*)QP;
    uint32_t qf[2][8][4];
    #pragma unroll
    for (int ks = 0; ks < 8; ks++) {
        const int kk = ks * 8 + tg;
        #pragma unroll
        for (int rc = 0; rc < 2; rc++) {
            const int r = wrow + 16 * rc + g;
            qf[rc][ks][0] = QPu[r * ALD + kk];
            qf[rc][ks][1] = QPu[(r + 8) * ALD + kk];
            qf[rc][ks][2] = QPu[r * ALD + kk + 4];
            qf[rc][ks][3] = QPu[(r + 8) * ALD + kk + 4];
        }
    }

    float m_i[4] = {-1e30f, -1e30f, -1e30f, -1e30f};
    float l_i[4] = {0.f, 0.f, 0.f, 0.f};
    float o[2][8][4];
    #pragma unroll
    for (int rc = 0; rc < 2; rc++)
        #pragma unroll
        for (int nt = 0; nt < 8; nt++)
            #pragma unroll
            for (int e = 0; e < 4; e++) o[rc][nt][e] = 0.f;

    const int nkt = m0 / 64 + 2;
    for (int kt = 0; kt < nkt; kt++) {
        const int j0 = kt * 64;
        asm volatile("cp.async.wait_group 0;" ::: "memory");
        __syncthreads();              // stage kt visible; stage (kt-1)&1 free
        if (kt + 1 < nkt) issue_kv(kt + 1);

        const int s = kt & 1;
        const uint32_t* Ksu = (const uint32_t*)(KV + s * KVSTG);
        const uint32_t* Vsu = (const uint32_t*)(KV + s * KVSTG + 64 * ALD);

        // ---- S = Q @ K^T ----
        float sacc[2][8][4];
        #pragma unroll
        for (int rc = 0; rc < 2; rc++)
            #pragma unroll
            for (int nt = 0; nt < 8; nt++)
                #pragma unroll
                for (int e = 0; e < 4; e++) sacc[rc][nt][e] = 0.f;

        #pragma unroll
        for (int ks = 0; ks < 8; ks++) {
            const int kk = ks * 8 + tg;
            #pragma unroll
            for (int nt = 0; nt < 8; nt++) {
                uint32_t b[2];
                b[0] = Ksu[(nt * 8 + g) * ALD + kk];
                b[1] = Ksu[(nt * 8 + g) * ALD + kk + 4];
                mma16n8k8(sacc[0][nt], qf[0][ks], b);
                mma16n8k8(sacc[1][nt], qf[1][ks], b);
            }
        }

        // ---- causal mask ----
        if (j0 + 63 > m0 + wrow) {
            #pragma unroll
            for (int rc = 0; rc < 2; rc++)
                #pragma unroll
                for (int nt = 0; nt < 8; nt++)
                    #pragma unroll
                    for (int e = 0; e < 4; e++) {
                        const int row = m0 + wrow + 16 * rc + g + (e >> 1) * 8;
                        const int key = j0 + nt * 8 + 2 * tg + (e & 1);
                        if (key > row) sacc[rc][nt][e] = -1e30f;
                    }
        }

        // ---- online softmax ----
        #pragma unroll
        for (int rc = 0; rc < 2; rc++) {
            #pragma unroll
            for (int r2 = 0; r2 < 2; r2++) {
                const int si = rc * 2 + r2;
                float mx = -1e30f;
                #pragma unroll
                for (int nt = 0; nt < 8; nt++)
                    mx = fmaxf(mx, fmaxf(sacc[rc][nt][r2 * 2], sacc[rc][nt][r2 * 2 + 1]));
                mx = fmaxf(mx, __shfl_xor_sync(0xffffffffu, mx, 1));
                mx = fmaxf(mx, __shfl_xor_sync(0xffffffffu, mx, 2));
                const float mn = fmaxf(m_i[si], mx);
                const float corr = __expf(m_i[si] - mn);
                m_i[si] = mn;
                float rs = 0.f;
                #pragma unroll
                for (int nt = 0; nt < 8; nt++) {
                    float p0 = __expf(sacc[rc][nt][r2 * 2]     - mn);
                    float p1 = __expf(sacc[rc][nt][r2 * 2 + 1] - mn);
                    sacc[rc][nt][r2 * 2]     = p0;
                    sacc[rc][nt][r2 * 2 + 1] = p1;
                    rs += p0 + p1;
                }
                rs += __shfl_xor_sync(0xffffffffu, rs, 1);
                rs += __shfl_xor_sync(0xffffffffu, rs, 2);
                l_i[si] = l_i[si] * corr + rs;
                #pragma unroll
                for (int nt = 0; nt < 8; nt++) {
                    o[rc][nt][r2 * 2]     *= corr;
                    o[rc][nt][r2 * 2 + 1] *= corr;
                }
            }
        }

        // ---- stage P into QP (warp-private rows) ----
        float* Ps = QP;
        #pragma unroll
        for (int rc = 0; rc < 2; rc++) {
            const int r = wrow + 16 * rc + g;
            #pragma unroll
            for (int nt = 0; nt < 8; nt++) {
                *(float2*)&Ps[r * ALD + nt * 8 + 2 * tg] =
                    make_float2(rna_tf32(sacc[rc][nt][0]), rna_tf32(sacc[rc][nt][1]));
                *(float2*)&Ps[(r + 8) * ALD + nt * 8 + 2 * tg] =
                    make_float2(rna_tf32(sacc[rc][nt][2]), rna_tf32(sacc[rc][nt][3]));
            }
        }
        __syncwarp();

        // ---- O += P @ V ----
        #pragma unroll
        for (int ks = 0; ks < 8; ks++) {
            const int kk = ks * 8 + tg;
            uint32_t a[2][4];
            #pragma unroll
            for (int rc = 0; rc < 2; rc++) {
                const int r = wrow + 16 * rc + g;
                a[rc][0] = QPu[r * ALD + kk];
                a[rc][1] = QPu[(r + 8) * ALD + kk];
                a[rc][2] = QPu[r * ALD + kk + 4];
                a[rc][3] = QPu[(r + 8) * ALD + kk + 4];
            }
            #pragma unroll
            for (int nt = 0; nt < 8; nt++) {
                uint32_t b[2];
                b[0] = Vsu[kk * VLD + nt * 8 + g];
                b[1] = Vsu[(kk + 4) * VLD + nt * 8 + g];
                mma16n8k8(o[0][nt], a[0], b);
                mma16n8k8(o[1][nt], a[1], b);
            }
        }
        __syncwarp();
    }

    // ---- normalize, round to tf32 (gemm<1> operand), write g_y ----
    const int b_ = bh >> 4;
    const int head = bh & 15;
    #pragma unroll
    for (int rc = 0; rc < 2; rc++) {
        #pragma unroll
        for (int r2 = 0; r2 < 2; r2++) {
            const float inv = 1.f / l_i[rc * 2 + r2];
            const int row = m0 + wrow + 16 * rc + g + r2 * 8;
            #pragma unroll
            for (int nt = 0; nt < 8; nt++) {
                float2 v;
                v.x = rna_tf32(o[rc][nt][r2 * 2]     * inv);
                v.y = rna_tf32(o[rc][nt][r2 * 2 + 1] * inv);
                *(float2*)&g_y[((size_t)(b_ * Tv + row)) * Cv + head * 64 + nt * 8 + 2 * tg] = v;
            }
        }
    }
}

// ---------------------------------------------------------------------------
extern "C" void kernel_launch(void* const* d_in, const int* in_sizes, int n_in,
                              void* d_out, int out_size)
{
    const float* x     = (const float*)d_in[0];
    const float* W_qkv = (const float*)d_in[1];
    const float* b_qkv = (const float*)d_in[2];
    const float* W_out = (const float*)d_in[3];
    const float* b_out = (const float*)d_in[4];
    float* out = (float*)d_out;

    float* xr; cudaGetSymbolAddress((void**)&xr, g_xr);
    float* wq; cudaGetSymbolAddress((void**)&wq, g_wq);
    float* wo; cudaGetSymbolAddress((void**)&wo, g_wo);

    cudaFuncSetAttribute(attn_mma_kernel,
                         cudaFuncAttributeMaxDynamicSharedMemorySize, ATTN_SMEM);
    cudaFuncSetAttribute(gemm_mma<0>,
                         cudaFuncAttributeMaxDynamicSharedMemorySize, GEMM_SMEM);
    cudaFuncSetAttribute(gemm_mma<1>,
                         cudaFuncAttributeMaxDynamicSharedMemorySize, GEMM_SMEM);

    // prep: tf32-round all GEMM operands once
    round_rna_kernel<<<2048, 256>>>((const float4*)x, (float4*)xr, Mrows * Cv / 4);
    round_rna_kernel<<<1024, 256>>>((const float4*)W_qkv, (float4*)wq, 3 * Cv * Cv / 4);
    round_rna_kernel<<<512, 256>>>((const float4*)W_out, (float4*)wo, Cv * Cv / 4);

    // 1) QKV projection
    gemm_mma<0><<<dim3(3 * Cv / 128, Mrows / 128), 256, GEMM_SMEM>>>(xr, wq, b_qkv, nullptr, 3 * Cv);

    // 2) causal flash attention
    attn_mma_kernel<<<dim3(Tv / 128, Bv * Hv), 128, ATTN_SMEM>>>();

    // 3) output projection
    gemm_mma<1><<<dim3(Cv / 128, Mrows / 128), 256, GEMM_SMEM>>>(nullptr, wo, b_out, out, Cv);
}

// round 8
// speedup vs baseline: 3.8461x; 1.0707x over previous
#include <cuda_runtime.h>
#include <math.h>
#include <stdint.h>

#define Bv 4
#define Tv 2048
#define Cv 1024
#define Hv 16
#define Dv 64
#define Mrows (Bv*Tv)   // 8192

// ---------------- scratch (device globals; allocation-free) ----------------
__device__ float g_q[Bv*Hv*Tv*Dv];    // [B,H,T,D] (tf32-rounded)
__device__ float g_k[Bv*Hv*Tv*Dv];
__device__ float g_v[Bv*Hv*Tv*Dv];
__device__ float g_y[Bv*Tv*Cv];       // attention output [B,T,C] (tf32-rounded)
__device__ float g_xr[Mrows*Cv];      // x, tf32-rounded
__device__ float g_wq[3*Cv*Cv];       // W_qkv, tf32-rounded
__device__ float g_wo[Cv*Cv];         // W_out, tf32-rounded

__device__ __forceinline__ float rna_tf32(float x) {
    uint32_t u;
    asm("cvt.rna.tf32.f32 %0, %1;" : "=r"(u) : "f"(x));
    return __uint_as_float(u);
}

__device__ __forceinline__ void mma16n8k8(float* c, const uint32_t* a, const uint32_t* b) {
    asm volatile(
        "mma.sync.aligned.m16n8k8.row.col.f32.tf32.tf32.f32 "
        "{%0,%1,%2,%3}, {%4,%5,%6,%7}, {%8,%9}, {%0,%1,%2,%3};"
        : "+f"(c[0]), "+f"(c[1]), "+f"(c[2]), "+f"(c[3])
        : "r"(a[0]), "r"(a[1]), "r"(a[2]), "r"(a[3]), "r"(b[0]), "r"(b[1]));
}

__device__ __forceinline__ void ldsm_x4(uint32_t* r, uint32_t addr) {
    asm volatile(
        "ldmatrix.sync.aligned.m8n8.x4.shared.b16 {%0,%1,%2,%3}, [%4];"
        : "=r"(r[0]), "=r"(r[1]), "=r"(r[2]), "=r"(r[3]) : "r"(addr));
}

__device__ __forceinline__ void cp_async16(uint32_t dst, const float* src) {
    asm volatile("cp.async.cg.shared.global [%0], [%1], 16;" :: "r"(dst), "l"(src) : "memory");
}

// ---------------- prep: tf32 rounding pass ----------------
__global__ void round_rna_kernel(const float4* __restrict__ src, float4* __restrict__ dst, int n4) {
    for (int i = blockIdx.x * blockDim.x + threadIdx.x; i < n4; i += gridDim.x * blockDim.x) {
        float4 v = src[i];
        v.x = rna_tf32(v.x); v.y = rna_tf32(v.y);
        v.z = rna_tf32(v.z); v.w = rna_tf32(v.w);
        dst[i] = v;
    }
}

// ---------------------------------------------------------------------------
// tf32 warp-MMA GEMM, 3-stage cp.async pipeline, ldmatrix A-fragments.
// C[M,N] = A[M,1024] @ W[1024,N] + bias. CTA 128x128, BK=32, 256 threads,
// warp tile 64x32. A smem [128][36] (rows at 16B-distinct banks for ldsm);
// W smem [32][136] (scalar b-frag reads, banks 8tg+g conflict-free).
// ---------------------------------------------------------------------------
#define BK 32
#define LDW 36
#define LDB 136
#define NSTG 3
#define GEMM_SMEM ((NSTG*128*LDW + NSTG*BK*LDB) * 4)   // 107520 B

template<int MODE>
__global__ void __launch_bounds__(256) gemm_mma(
    const float* __restrict__ A_in, const float* __restrict__ W,
    const float* __restrict__ bias, float* __restrict__ out, int ldw)
{
    extern __shared__ float smg[];
    float* As = smg;                       // [NSTG][128*36]
    float* Bs = smg + NSTG * 128 * LDW;    // [NSTG][32*136]

    const float* A = (MODE == 1) ? g_y : A_in;

    const int tid  = threadIdx.x;
    const int lane = tid & 31;
    const int wid  = tid >> 5;
    const int wm   = (wid & 1) * 64;
    const int wn   = (wid >> 1) * 32;
    const int g    = lane >> 2;
    const int tg   = lane & 3;

    const int row0 = blockIdx.y * 128;
    const int col0 = blockIdx.x * 128;
    const float* Ab = A + (size_t)row0 * Cv;
    const float* Wb = W + col0;

    const int ar = tid >> 3;
    const int ac = (tid & 7) << 2;
    const int br = tid >> 5;
    const int bc = (tid & 31) << 2;

    const uint32_t aBase = (uint32_t)__cvta_generic_to_shared(As);
    const uint32_t bBase = (uint32_t)__cvta_generic_to_shared(Bs);

    // ldmatrix per-lane addressing for A fragments (m16k8 tiles)
    const int lrow  = lane & 15;            // tile row offset
    const int lcolw = (lane >> 4) << 2;     // tile col offset (words)
    const uint32_t aFragBase = aBase + (uint32_t)(((wm + lrow) * LDW + lcolw) * 4);

    float c[4][4][4];
    #pragma unroll
    for (int mt = 0; mt < 4; mt++)
        #pragma unroll
        for (int nt = 0; nt < 4; nt++)
            #pragma unroll
            for (int i = 0; i < 4; i++) c[mt][nt][i] = 0.f;

    const int NC = Cv / BK;   // 32

    auto issue = [&](int ch) {
        if (ch < NC) {
            const int s = ch % NSTG;
            const float* gA = Ab + ch * BK;
            const float* gW = Wb + (size_t)ch * BK * ldw;
            const uint32_t ab = aBase + (uint32_t)(s * 128 * LDW * 4);
            const uint32_t bb = bBase + (uint32_t)(s * BK * LDB * 4);
            #pragma unroll
            for (int i = 0; i < 4; i++) {
                cp_async16(ab + (uint32_t)(((ar + i * 32) * LDW + ac) * 4),
                           gA + (size_t)(ar + i * 32) * Cv + ac);
                cp_async16(bb + (uint32_t)(((br + i * 8) * LDB + bc) * 4),
                           gW + (size_t)(br + i * 8) * ldw + bc);
            }
        }
        asm volatile("cp.async.commit_group;" ::: "memory");
    };

    issue(0);
    issue(1);

    for (int ch = 0; ch < NC; ch++) {
        asm volatile("cp.async.wait_group 1;" ::: "memory");
        __syncthreads();
        issue(ch + 2);

        const int s = ch % NSTG;
        const uint32_t aStage = aFragBase + (uint32_t)(s * 128 * LDW * 4);
        const uint32_t* Bsu = (const uint32_t*)(Bs + s * BK * LDB);

        #pragma unroll
        for (int ks = 0; ks < 4; ks++) {
            const int kk = ks * 8 + tg;
            uint32_t a[4][4];
            #pragma unroll
            for (int mt = 0; mt < 4; mt++)
                ldsm_x4(a[mt], aStage + (uint32_t)(mt * 16 * LDW * 4 + ks * 32));
            uint32_t b[4][2];
            #pragma unroll
            for (int nt = 0; nt < 4; nt++) {
                const int n = wn + nt * 8 + g;
                b[nt][0] = Bsu[kk * LDB + n];
                b[nt][1] = Bsu[(kk + 4) * LDB + n];
            }
            #pragma unroll
            for (int mt = 0; mt < 4; mt++)
                #pragma unroll
                for (int nt = 0; nt < 4; nt++)
                    mma16n8k8(c[mt][nt], a[mt], b[nt]);
        }
    }

    #pragma unroll
    for (int mt = 0; mt < 4; mt++) {
        #pragma unroll
        for (int r2 = 0; r2 < 2; r2++) {
            const int row = row0 + wm + mt * 16 + g + r2 * 8;
            const int b_ = row >> 11, t_ = row & 2047;
            #pragma unroll
            for (int nt = 0; nt < 4; nt++) {
                const int col = col0 + wn + nt * 8 + tg * 2;
                float2 v;
                v.x = c[mt][nt][r2 * 2 + 0] + __ldg(bias + col + 0);
                v.y = c[mt][nt][r2 * 2 + 1] + __ldg(bias + col + 1);
                if (MODE == 0) {
                    v.x = rna_tf32(v.x);
                    v.y = rna_tf32(v.y);
                    const int which = col >> 10;
                    const int cc = col & 1023;
                    const int h = cc >> 6, d = cc & 63;
                    float* dst = (which == 0) ? g_q : (which == 1) ? g_k : g_v;
                    *(float2*)&dst[((size_t)((b_ * Hv + h) * Tv + t_)) * Dv + d] = v;
                } else {
                    *(float2*)&out[(size_t)row * Cv + col] = v;
                }
            }
        }
    }
}

// ---------------------------------------------------------------------------
// Flash attention on mma.sync tf32.
// CTA: 128 q-rows, 4 warps x 32 rows, 64 keys/iter.
// K/V double-buffered cp.async, one barrier per k-tile. Q frags in regs.
// ldmatrix for K-frags (B of QK) and P-frags (A of PV); V scalar.
// ---------------------------------------------------------------------------
#define ALD 68
#define VLD 72
#define KVSTG (64*ALD + 64*VLD)
#define ATTN_SMEM ((128*ALD + 2*KVSTG) * 4)   // 106496 B

__global__ void __launch_bounds__(128) attn_mma_kernel()
{
    extern __shared__ float sm[];
    float* QP = sm;                    // [128][68]: Q during prologue, P after
    float* KV = sm + 128 * ALD;

    const uint32_t qpBase = (uint32_t)__cvta_generic_to_shared(QP);
    const uint32_t kvBase = (uint32_t)__cvta_generic_to_shared(KV);

    const int tid  = threadIdx.x;
    const int lane = tid & 31;
    const int w    = tid >> 5;
    const int g    = lane >> 2;
    const int tg   = lane & 3;

    const int bh = blockIdx.y;
    const int m0 = blockIdx.x * 128;

    const float* qp = g_q + (size_t)bh * Tv * Dv;
    const float* kp = g_k + (size_t)bh * Tv * Dv;
    const float* vp = g_v + (size_t)bh * Tv * Dv;

    auto issue_kv = [&](int kt) {
        const int s = kt & 1;
        const float* kpt = kp + (size_t)(kt * 64) * Dv;
        const float* vpt = vp + (size_t)(kt * 64) * Dv;
        const uint32_t kb = kvBase + (uint32_t)(s * KVSTG * 4);
        const uint32_t vb = kb + (uint32_t)(64 * ALD * 4);
        #pragma unroll
        for (int i = 0; i < 8; i++) {
            const int f = i * 128 + tid;
            const int r = f >> 4, c4 = (f & 15) << 2;
            cp_async16(kb + (uint32_t)((r * ALD + c4) * 4), kpt + r * Dv + c4);
            cp_async16(vb + (uint32_t)((r * VLD + c4) * 4), vpt + r * Dv + c4);
        }
        asm volatile("cp.async.commit_group;" ::: "memory");
    };

    issue_kv(0);

    // Load Q tile into QP (pre-rounded; 0.125 exact)
    #pragma unroll
    for (int i = 0; i < 16; i++) {
        const int f = i * 128 + tid;
        const int r = f >> 4, c4 = (f & 15) << 2;
        float4 v = *(const float4*)(qp + (size_t)(m0 + r) * Dv + c4);
        v.x *= 0.125f; v.y *= 0.125f; v.z *= 0.125f; v.w *= 0.125f;
        *(float4*)&QP[r * ALD + c4] = v;
    }
    __syncthreads();

    const int wrow = 32 * w;

    // ldmatrix lane addressing
    const int lrow  = lane & 15;               // A-pattern (Q/P tiles)
    const int lcolw = (lane >> 4) << 2;
    const int brow  = (lane & 7) + ((lane & 16) ? 8 : 0);   // B-pattern (K tiles)
    const int bcolw = ((lane >> 3) & 1) << 2;

    // Hoist Q fragments via ldmatrix; QP becomes P staging after this.
    uint32_t qf[2][8][4];
    {
        const uint32_t qFragBase = qpBase + (uint32_t)(((wrow + lrow) * ALD + lcolw) * 4);
        #pragma unroll
        for (int ks = 0; ks < 8; ks++) {
            ldsm_x4(qf[0][ks], qFragBase + (uint32_t)(ks * 32));
            ldsm_x4(qf[1][ks], qFragBase + (uint32_t)(16 * ALD * 4 + ks * 32));
        }
    }
    const uint32_t pFragBase = qpBase + (uint32_t)(((wrow + lrow) * ALD + lcolw) * 4);

    float m_i[4] = {-1e30f, -1e30f, -1e30f, -1e30f};
    float l_i[4] = {0.f, 0.f, 0.f, 0.f};
    float o[2][8][4];
    #pragma unroll
    for (int rc = 0; rc < 2; rc++)
        #pragma unroll
        for (int nt = 0; nt < 8; nt++)
            #pragma unroll
            for (int e = 0; e < 4; e++) o[rc][nt][e] = 0.f;

    const int nkt = m0 / 64 + 2;
    for (int kt = 0; kt < nkt; kt++) {
        const int j0 = kt * 64;
        asm volatile("cp.async.wait_group 0;" ::: "memory");
        __syncthreads();
        if (kt + 1 < nkt) issue_kv(kt + 1);

        const int s = kt & 1;
        const uint32_t kFragBase = kvBase + (uint32_t)(s * KVSTG * 4)
                                 + (uint32_t)((brow * ALD + bcolw) * 4);
        const uint32_t* Vsu = (const uint32_t*)(KV + s * KVSTG + 64 * ALD);

        // ---- S = Q @ K^T (K frags via ldsm.x4, 2 n-tiles per call) ----
        float sacc[2][8][4];
        #pragma unroll
        for (int rc = 0; rc < 2; rc++)
            #pragma unroll
            for (int nt = 0; nt < 8; nt++)
                #pragma unroll
                for (int e = 0; e < 4; e++) sacc[rc][nt][e] = 0.f;

        #pragma unroll
        for (int ks = 0; ks < 8; ks++) {
            #pragma unroll
            for (int ntp = 0; ntp < 4; ntp++) {
                uint32_t bb[4];   // {b[2ntp][0], b[2ntp][1], b[2ntp+1][0], b[2ntp+1][1]}
                ldsm_x4(bb, kFragBase + (uint32_t)(ntp * 16 * ALD * 4 + ks * 32));
                mma16n8k8(sacc[0][2 * ntp],     qf[0][ks], bb);
                mma16n8k8(sacc[1][2 * ntp],     qf[1][ks], bb);
                mma16n8k8(sacc[0][2 * ntp + 1], qf[0][ks], bb + 2);
                mma16n8k8(sacc[1][2 * ntp + 1], qf[1][ks], bb + 2);
            }
        }

        // ---- causal mask ----
        if (j0 + 63 > m0 + wrow) {
            #pragma unroll
            for (int rc = 0; rc < 2; rc++)
                #pragma unroll
                for (int nt = 0; nt < 8; nt++)
                    #pragma unroll
                    for (int e = 0; e < 4; e++) {
                        const int row = m0 + wrow + 16 * rc + g + (e >> 1) * 8;
                        const int key = j0 + nt * 8 + 2 * tg + (e & 1);
                        if (key > row) sacc[rc][nt][e] = -1e30f;
                    }
        }

        // ---- online softmax ----
        #pragma unroll
        for (int rc = 0; rc < 2; rc++) {
            #pragma unroll
            for (int r2 = 0; r2 < 2; r2++) {
                const int si = rc * 2 + r2;
                float mx = -1e30f;
                #pragma unroll
                for (int nt = 0; nt < 8; nt++)
                    mx = fmaxf(mx, fmaxf(sacc[rc][nt][r2 * 2], sacc[rc][nt][r2 * 2 + 1]));
                mx = fmaxf(mx, __shfl_xor_sync(0xffffffffu, mx, 1));
                mx = fmaxf(mx, __shfl_xor_sync(0xffffffffu, mx, 2));
                const float mn = fmaxf(m_i[si], mx);
                const float corr = __expf(m_i[si] - mn);
                m_i[si] = mn;
                float rs = 0.f;
                #pragma unroll
                for (int nt = 0; nt < 8; nt++) {
                    float p0 = __expf(sacc[rc][nt][r2 * 2]     - mn);
                    float p1 = __expf(sacc[rc][nt][r2 * 2 + 1] - mn);
                    sacc[rc][nt][r2 * 2]     = p0;
                    sacc[rc][nt][r2 * 2 + 1] = p1;
                    rs += p0 + p1;
                }
                rs += __shfl_xor_sync(0xffffffffu, rs, 1);
                rs += __shfl_xor_sync(0xffffffffu, rs, 2);
                l_i[si] = l_i[si] * corr + rs;
                #pragma unroll
                for (int nt = 0; nt < 8; nt++) {
                    o[rc][nt][r2 * 2]     *= corr;
                    o[rc][nt][r2 * 2 + 1] *= corr;
                }
            }
        }

        // ---- stage P into QP (warp-private rows) ----
        float* Ps = QP;
        #pragma unroll
        for (int rc = 0; rc < 2; rc++) {
            const int r = wrow + 16 * rc + g;
            #pragma unroll
            for (int nt = 0; nt < 8; nt++) {
                *(float2*)&Ps[r * ALD + nt * 8 + 2 * tg] =
                    make_float2(rna_tf32(sacc[rc][nt][0]), rna_tf32(sacc[rc][nt][1]));
                *(float2*)&Ps[(r + 8) * ALD + nt * 8 + 2 * tg] =
                    make_float2(rna_tf32(sacc[rc][nt][2]), rna_tf32(sacc[rc][nt][3]));
            }
        }
        __syncwarp();

        // ---- O += P @ V (P frags via ldsm.x4; V scalar, conflict-free) ----
        #pragma unroll
        for (int ks = 0; ks < 8; ks++) {
            const int kk = ks * 8 + tg;
            uint32_t a[2][4];
            ldsm_x4(a[0], pFragBase + (uint32_t)(ks * 32));
            ldsm_x4(a[1], pFragBase + (uint32_t)(16 * ALD * 4 + ks * 32));
            #pragma unroll
            for (int nt = 0; nt < 8; nt++) {
                uint32_t b[2];
                b[0] = Vsu[kk * VLD + nt * 8 + g];
                b[1] = Vsu[(kk + 4) * VLD + nt * 8 + g];
                mma16n8k8(o[0][nt], a[0], b);
                mma16n8k8(o[1][nt], a[1], b);
            }
        }
        __syncwarp();
    }

    // ---- normalize, round to tf32 (gemm<1> operand), write g_y ----
    const int b_ = bh >> 4;
    const int head = bh & 15;
    #pragma unroll
    for (int rc = 0; rc < 2; rc++) {
        #pragma unroll
        for (int r2 = 0; r2 < 2; r2++) {
            const float inv = 1.f / l_i[rc * 2 + r2];
            const int row = m0 + wrow + 16 * rc + g + r2 * 8;
            #pragma unroll
            for (int nt = 0; nt < 8; nt++) {
                float2 v;
                v.x = rna_tf32(o[rc][nt][r2 * 2]     * inv);
                v.y = rna_tf32(o[rc][nt][r2 * 2 + 1] * inv);
                *(float2*)&g_y[((size_t)(b_ * Tv + row)) * Cv + head * 64 + nt * 8 + 2 * tg] = v;
            }
        }
    }
}

// ---------------------------------------------------------------------------
extern "C" void kernel_launch(void* const* d_in, const int* in_sizes, int n_in,
                              void* d_out, int out_size)
{
    const float* x     = (const float*)d_in[0];
    const float* W_qkv = (const float*)d_in[1];
    const float* b_qkv = (const float*)d_in[2];
    const float* W_out = (const float*)d_in[3];
    const float* b_out = (const float*)d_in[4];
    float* out = (float*)d_out;

    float* xr; cudaGetSymbolAddress((void**)&xr, g_xr);
    float* wq; cudaGetSymbolAddress((void**)&wq, g_wq);
    float* wo; cudaGetSymbolAddress((void**)&wo, g_wo);

    cudaFuncSetAttribute(attn_mma_kernel,
                         cudaFuncAttributeMaxDynamicSharedMemorySize, ATTN_SMEM);
    cudaFuncSetAttribute(gemm_mma<0>,
                         cudaFuncAttributeMaxDynamicSharedMemorySize, GEMM_SMEM);
    cudaFuncSetAttribute(gemm_mma<1>,
                         cudaFuncAttributeMaxDynamicSharedMemorySize, GEMM_SMEM);

    // prep: tf32-round all GEMM operands once
    round_rna_kernel<<<2048, 256>>>((const float4*)x, (float4*)xr, Mrows * Cv / 4);
    round_rna_kernel<<<1024, 256>>>((const float4*)W_qkv, (float4*)wq, 3 * Cv * Cv / 4);
    round_rna_kernel<<<512, 256>>>((const float4*)W_out, (float4*)wo, Cv * Cv / 4);

    // 1) QKV projection
    gemm_mma<0><<<dim3(3 * Cv / 128, Mrows / 128), 256, GEMM_SMEM>>>(xr, wq, b_qkv, nullptr, 3 * Cv);

    // 2) causal flash attention
    attn_mma_kernel<<<dim3(Tv / 128, Bv * Hv), 128, ATTN_SMEM>>>();

    // 3) output projection
    gemm_mma<1><<<dim3(Cv / 128, Mrows / 128), 256, GEMM_SMEM>>>(nullptr, wo, b_out, out, Cv);
}

// round 9
// speedup vs baseline: 3.8651x; 1.0049x over previous
#include <cuda_runtime.h>
#include <math.h>
#include <stdint.h>

#define Bv 4
#define Tv 2048
#define Cv 1024
#define Hv 16
#define Dv 64
#define Mrows (Bv*Tv)   // 8192

// ---------------- scratch (device globals; allocation-free) ----------------
__device__ float g_q[Bv*Hv*Tv*Dv];    // [B,H,T,D] (tf32-rounded)
__device__ float g_k[Bv*Hv*Tv*Dv];
__device__ float g_v[Bv*Hv*Tv*Dv];
__device__ float g_y[Bv*Tv*Cv];       // attention output [B,T,C] (tf32-rounded)
__device__ float g_xr[Mrows*Cv];      // x, tf32-rounded
__device__ float g_wqT[3*Cv*Cv];      // W_qkv^T [3072][1024], tf32-rounded
__device__ float g_woT[Cv*Cv];        // W_out^T [1024][1024], tf32-rounded

__device__ __forceinline__ float rna_tf32(float x) {
    uint32_t u;
    asm("cvt.rna.tf32.f32 %0, %1;" : "=r"(u) : "f"(x));
    return __uint_as_float(u);
}

__device__ __forceinline__ void mma16n8k8(float* c, const uint32_t* a, const uint32_t* b) {
    asm volatile(
        "mma.sync.aligned.m16n8k8.row.col.f32.tf32.tf32.f32 "
        "{%0,%1,%2,%3}, {%4,%5,%6,%7}, {%8,%9}, {%0,%1,%2,%3};"
        : "+f"(c[0]), "+f"(c[1]), "+f"(c[2]), "+f"(c[3])
        : "r"(a[0]), "r"(a[1]), "r"(a[2]), "r"(a[3]), "r"(b[0]), "r"(b[1]));
}

__device__ __forceinline__ void ldsm_x4(uint32_t* r, uint32_t addr) {
    asm volatile(
        "ldmatrix.sync.aligned.m8n8.x4.shared.b16 {%0,%1,%2,%3}, [%4];"
        : "=r"(r[0]), "=r"(r[1]), "=r"(r[2]), "=r"(r[3]) : "r"(addr));
}

__device__ __forceinline__ void cp_async16(uint32_t dst, const float* src) {
    asm volatile("cp.async.cg.shared.global [%0], [%1], 16;" :: "r"(dst), "l"(src) : "memory");
}

// ---------------- prep kernels ----------------
__global__ void round_rna_kernel(const float4* __restrict__ src, float4* __restrict__ dst, int n4) {
    for (int i = blockIdx.x * blockDim.x + threadIdx.x; i < n4; i += gridDim.x * blockDim.x) {
        float4 v = src[i];
        v.x = rna_tf32(v.x); v.y = rna_tf32(v.y);
        v.z = rna_tf32(v.z); v.w = rna_tf32(v.w);
        dst[i] = v;
    }
}
// dst[n][k] = rna(src[k][n]); src is [K][N]
__global__ void transpose_rna_kernel(const float* __restrict__ src, float* __restrict__ dst,
                                     int K, int N) {
    __shared__ float t[32][33];
    int n0 = blockIdx.x * 32, k0 = blockIdx.y * 32;
    #pragma unroll
    for (int i = 0; i < 32; i += 8)
        t[threadIdx.y + i][threadIdx.x] =
            src[(size_t)(k0 + threadIdx.y + i) * N + n0 + threadIdx.x];
    __syncthreads();
    #pragma unroll
    for (int i = 0; i < 32; i += 8)
        dst[(size_t)(n0 + threadIdx.y + i) * K + k0 + threadIdx.x] =
            rna_tf32(t[threadIdx.x][threadIdx.y + i]);
}

// ---------------------------------------------------------------------------
// tf32 warp-MMA GEMM, 3-stage cp.async pipeline, FULL ldmatrix fragments.
// C[M,N] = A[M,1024] @ Wt[N,1024]^T + bias (Wt pre-transposed + rounded).
// CTA 128x128, BK=32, 256 threads, warp tile 64x32.
// Both smem tiles [128][36]: 16B-distinct row banks -> conflict-free ldsm.
// Per ks: 4 A-ldsm.x4 + 2 B-ldsm.x4 + 16 HMMA.
// ---------------------------------------------------------------------------
#define BK 32
#define LDW 36
#define NSTG 3
#define TILEW (128*LDW)                       // floats per operand tile
#define GEMM_SMEM (NSTG * 2 * TILEW * 4)      // 110592 B

template<int MODE>
__global__ void __launch_bounds__(256) gemm_mma(
    const float* __restrict__ A_in, const float* __restrict__ Wt,
    const float* __restrict__ bias, float* __restrict__ out)
{
    extern __shared__ float smg[];
    float* As = smg;                   // [NSTG][128*36]
    float* Bs = smg + NSTG * TILEW;    // [NSTG][128*36]

    const float* A = (MODE == 1) ? g_y : A_in;

    const int tid  = threadIdx.x;
    const int lane = tid & 31;
    const int wid  = tid >> 5;
    const int wm   = (wid & 1) * 64;
    const int wn   = (wid >> 1) * 32;
    const int g    = lane >> 2;
    const int tg   = lane & 3;

    const int row0 = blockIdx.y * 128;
    const int col0 = blockIdx.x * 128;
    const float* Ab = A  + (size_t)row0 * Cv;
    const float* Bb = Wt + (size_t)col0 * Cv;

    const int gr = tid >> 3;            // granule row (0..31, x4 iters -> 128)
    const int gc = (tid & 7) << 2;      // granule k-col

    const uint32_t aBase = (uint32_t)__cvta_generic_to_shared(As);
    const uint32_t bBase = (uint32_t)__cvta_generic_to_shared(Bs);

    // ldmatrix lane addressing
    const int lrow  = lane & 15;                             // A-pattern
    const int lcolw = (lane >> 4) << 2;
    const int brow  = (lane & 7) + ((lane & 16) ? 8 : 0);    // B-pattern
    const int bcolw = ((lane >> 3) & 1) << 2;
    const uint32_t aFragBase = aBase + (uint32_t)(((wm + lrow) * LDW + lcolw) * 4);
    const uint32_t bFragBase = bBase + (uint32_t)(((wn + brow) * LDW + bcolw) * 4);

    float c[4][4][4];
    #pragma unroll
    for (int mt = 0; mt < 4; mt++)
        #pragma unroll
        for (int nt = 0; nt < 4; nt++)
            #pragma unroll
            for (int i = 0; i < 4; i++) c[mt][nt][i] = 0.f;

    const int NC = Cv / BK;   // 32

    auto issue = [&](int ch) {
        if (ch < NC) {
            const int s = ch % NSTG;
            const float* gA = Ab + ch * BK;
            const float* gB = Bb + ch * BK;
            const uint32_t ab = aBase + (uint32_t)(s * TILEW * 4);
            const uint32_t bb = bBase + (uint32_t)(s * TILEW * 4);
            #pragma unroll
            for (int i = 0; i < 4; i++) {
                const int r = gr + i * 32;
                const uint32_t off = (uint32_t)((r * LDW + gc) * 4);
                cp_async16(ab + off, gA + (size_t)r * Cv + gc);
                cp_async16(bb + off, gB + (size_t)r * Cv + gc);
            }
        }
        asm volatile("cp.async.commit_group;" ::: "memory");
    };

    issue(0);
    issue(1);

    for (int ch = 0; ch < NC; ch++) {
        asm volatile("cp.async.wait_group 1;" ::: "memory");
        __syncthreads();
        issue(ch + 2);

        const int s = ch % NSTG;
        const uint32_t aStage = aFragBase + (uint32_t)(s * TILEW * 4);
        const uint32_t bStage = bFragBase + (uint32_t)(s * TILEW * 4);

        #pragma unroll
        for (int ks = 0; ks < 4; ks++) {
            uint32_t a[4][4];
            #pragma unroll
            for (int mt = 0; mt < 4; mt++)
                ldsm_x4(a[mt], aStage + (uint32_t)(mt * 16 * LDW * 4 + ks * 32));
            uint32_t b[2][4];    // [ntp] -> {b(2ntp)0, b(2ntp)1, b(2ntp+1)0, b(2ntp+1)1}
            #pragma unroll
            for (int ntp = 0; ntp < 2; ntp++)
                ldsm_x4(b[ntp], bStage + (uint32_t)(ntp * 16 * LDW * 4 + ks * 32));
            #pragma unroll
            for (int mt = 0; mt < 4; mt++)
                #pragma unroll
                for (int nt = 0; nt < 4; nt++)
                    mma16n8k8(c[mt][nt], a[mt], b[nt >> 1] + (nt & 1) * 2);
        }
    }

    #pragma unroll
    for (int mt = 0; mt < 4; mt++) {
        #pragma unroll
        for (int r2 = 0; r2 < 2; r2++) {
            const int row = row0 + wm + mt * 16 + g + r2 * 8;
            const int b_ = row >> 11, t_ = row & 2047;
            #pragma unroll
            for (int nt = 0; nt < 4; nt++) {
                const int col = col0 + wn + nt * 8 + tg * 2;
                float2 v;
                v.x = c[mt][nt][r2 * 2 + 0] + __ldg(bias + col + 0);
                v.y = c[mt][nt][r2 * 2 + 1] + __ldg(bias + col + 1);
                if (MODE == 0) {
                    v.x = rna_tf32(v.x);
                    v.y = rna_tf32(v.y);
                    const int which = col >> 10;
                    const int cc = col & 1023;
                    const int h = cc >> 6, d = cc & 63;
                    float* dst = (which == 0) ? g_q : (which == 1) ? g_k : g_v;
                    *(float2*)&dst[((size_t)((b_ * Hv + h) * Tv + t_)) * Dv + d] = v;
                } else {
                    *(float2*)&out[(size_t)row * Cv + col] = v;
                }
            }
        }
    }
}

// ---------------------------------------------------------------------------
// Flash attention on mma.sync tf32 (unchanged from Round 8).
// ---------------------------------------------------------------------------
#define ALD 68
#define VLD 72
#define KVSTG (64*ALD + 64*VLD)
#define ATTN_SMEM ((128*ALD + 2*KVSTG) * 4)   // 106496 B

__global__ void __launch_bounds__(128) attn_mma_kernel()
{
    extern __shared__ float sm[];
    float* QP = sm;
    float* KV = sm + 128 * ALD;

    const uint32_t qpBase = (uint32_t)__cvta_generic_to_shared(QP);
    const uint32_t kvBase = (uint32_t)__cvta_generic_to_shared(KV);

    const int tid  = threadIdx.x;
    const int lane = tid & 31;
    const int w    = tid >> 5;
    const int g    = lane >> 2;
    const int tg   = lane & 3;

    const int bh = blockIdx.y;
    const int m0 = blockIdx.x * 128;

    const float* qp = g_q + (size_t)bh * Tv * Dv;
    const float* kp = g_k + (size_t)bh * Tv * Dv;
    const float* vp = g_v + (size_t)bh * Tv * Dv;

    auto issue_kv = [&](int kt) {
        const int s = kt & 1;
        const float* kpt = kp + (size_t)(kt * 64) * Dv;
        const float* vpt = vp + (size_t)(kt * 64) * Dv;
        const uint32_t kb = kvBase + (uint32_t)(s * KVSTG * 4);
        const uint32_t vb = kb + (uint32_t)(64 * ALD * 4);
        #pragma unroll
        for (int i = 0; i < 8; i++) {
            const int f = i * 128 + tid;
            const int r = f >> 4, c4 = (f & 15) << 2;
            cp_async16(kb + (uint32_t)((r * ALD + c4) * 4), kpt + r * Dv + c4);
            cp_async16(vb + (uint32_t)((r * VLD + c4) * 4), vpt + r * Dv + c4);
        }
        asm volatile("cp.async.commit_group;" ::: "memory");
    };

    issue_kv(0);

    #pragma unroll
    for (int i = 0; i < 16; i++) {
        const int f = i * 128 + tid;
        const int r = f >> 4, c4 = (f & 15) << 2;
        float4 v = *(const float4*)(qp + (size_t)(m0 + r) * Dv + c4);
        v.x *= 0.125f; v.y *= 0.125f; v.z *= 0.125f; v.w *= 0.125f;
        *(float4*)&QP[r * ALD + c4] = v;
    }
    __syncthreads();

    const int wrow = 32 * w;

    const int lrow  = lane & 15;
    const int lcolw = (lane >> 4) << 2;
    const int brow  = (lane & 7) + ((lane & 16) ? 8 : 0);
    const int bcolw = ((lane >> 3) & 1) << 2;

    uint32_t qf[2][8][4];
    {
        const uint32_t qFragBase = qpBase + (uint32_t)(((wrow + lrow) * ALD + lcolw) * 4);
        #pragma unroll
        for (int ks = 0; ks < 8; ks++) {
            ldsm_x4(qf[0][ks], qFragBase + (uint32_t)(ks * 32));
            ldsm_x4(qf[1][ks], qFragBase + (uint32_t)(16 * ALD * 4 + ks * 32));
        }
    }
    const uint32_t pFragBase = qpBase + (uint32_t)(((wrow + lrow) * ALD + lcolw) * 4);

    float m_i[4] = {-1e30f, -1e30f, -1e30f, -1e30f};
    float l_i[4] = {0.f, 0.f, 0.f, 0.f};
    float o[2][8][4];
    #pragma unroll
    for (int rc = 0; rc < 2; rc++)
        #pragma unroll
        for (int nt = 0; nt < 8; nt++)
            #pragma unroll
            for (int e = 0; e < 4; e++) o[rc][nt][e] = 0.f;

    const int nkt = m0 / 64 + 2;
    for (int kt = 0; kt < nkt; kt++) {
        const int j0 = kt * 64;
        asm volatile("cp.async.wait_group 0;" ::: "memory");
        __syncthreads();
        if (kt + 1 < nkt) issue_kv(kt + 1);

        const int s = kt & 1;
        const uint32_t kFragBase = kvBase + (uint32_t)(s * KVSTG * 4)
                                 + (uint32_t)((brow * ALD + bcolw) * 4);
        const uint32_t* Vsu = (const uint32_t*)(KV + s * KVSTG + 64 * ALD);

        float sacc[2][8][4];
        #pragma unroll
        for (int rc = 0; rc < 2; rc++)
            #pragma unroll
            for (int nt = 0; nt < 8; nt++)
                #pragma unroll
                for (int e = 0; e < 4; e++) sacc[rc][nt][e] = 0.f;

        #pragma unroll
        for (int ks = 0; ks < 8; ks++) {
            #pragma unroll
            for (int ntp = 0; ntp < 4; ntp++) {
                uint32_t bb[4];
                ldsm_x4(bb, kFragBase + (uint32_t)(ntp * 16 * ALD * 4 + ks * 32));
                mma16n8k8(sacc[0][2 * ntp],     qf[0][ks], bb);
                mma16n8k8(sacc[1][2 * ntp],     qf[1][ks], bb);
                mma16n8k8(sacc[0][2 * ntp + 1], qf[0][ks], bb + 2);
                mma16n8k8(sacc[1][2 * ntp + 1], qf[1][ks], bb + 2);
            }
        }

        if (j0 + 63 > m0 + wrow) {
            #pragma unroll
            for (int rc = 0; rc < 2; rc++)
                #pragma unroll
                for (int nt = 0; nt < 8; nt++)
                    #pragma unroll
                    for (int e = 0; e < 4; e++) {
                        const int row = m0 + wrow + 16 * rc + g + (e >> 1) * 8;
                        const int key = j0 + nt * 8 + 2 * tg + (e & 1);
                        if (key > row) sacc[rc][nt][e] = -1e30f;
                    }
        }

        #pragma unroll
        for (int rc = 0; rc < 2; rc++) {
            #pragma unroll
            for (int r2 = 0; r2 < 2; r2++) {
                const int si = rc * 2 + r2;
                float mx = -1e30f;
                #pragma unroll
                for (int nt = 0; nt < 8; nt++)
                    mx = fmaxf(mx, fmaxf(sacc[rc][nt][r2 * 2], sacc[rc][nt][r2 * 2 + 1]));
                mx = fmaxf(mx, __shfl_xor_sync(0xffffffffu, mx, 1));
                mx = fmaxf(mx, __shfl_xor_sync(0xffffffffu, mx, 2));
                const float mn = fmaxf(m_i[si], mx);
                const float corr = __expf(m_i[si] - mn);
                m_i[si] = mn;
                float rs = 0.f;
                #pragma unroll
                for (int nt = 0; nt < 8; nt++) {
                    float p0 = __expf(sacc[rc][nt][r2 * 2]     - mn);
                    float p1 = __expf(sacc[rc][nt][r2 * 2 + 1] - mn);
                    sacc[rc][nt][r2 * 2]     = p0;
                    sacc[rc][nt][r2 * 2 + 1] = p1;
                    rs += p0 + p1;
                }
                rs += __shfl_xor_sync(0xffffffffu, rs, 1);
                rs += __shfl_xor_sync(0xffffffffu, rs, 2);
                l_i[si] = l_i[si] * corr + rs;
                #pragma unroll
                for (int nt = 0; nt < 8; nt++) {
                    o[rc][nt][r2 * 2]     *= corr;
                    o[rc][nt][r2 * 2 + 1] *= corr;
                }
            }
        }

        float* Ps = QP;
        #pragma unroll
        for (int rc = 0; rc < 2; rc++) {
            const int r = wrow + 16 * rc + g;
            #pragma unroll
            for (int nt = 0; nt < 8; nt++) {
                *(float2*)&Ps[r * ALD + nt * 8 + 2 * tg] =
                    make_float2(rna_tf32(sacc[rc][nt][0]), rna_tf32(sacc[rc][nt][1]));
                *(float2*)&Ps[(r + 8) * ALD + nt * 8 + 2 * tg] =
                    make_float2(rna_tf32(sacc[rc][nt][2]), rna_tf32(sacc[rc][nt][3]));
            }
        }
        __syncwarp();

        #pragma unroll
        for (int ks = 0; ks < 8; ks++) {
            const int kk = ks * 8 + tg;
            uint32_t a[2][4];
            ldsm_x4(a[0], pFragBase + (uint32_t)(ks * 32));
            ldsm_x4(a[1], pFragBase + (uint32_t)(16 * ALD * 4 + ks * 32));
            #pragma unroll
            for (int nt = 0; nt < 8; nt++) {
                uint32_t b[2];
                b[0] = Vsu[kk * VLD + nt * 8 + g];
                b[1] = Vsu[(kk + 4) * VLD + nt * 8 + g];
                mma16n8k8(o[0][nt], a[0], b);
                mma16n8k8(o[1][nt], a[1], b);
            }
        }
        __syncwarp();
    }

    const int b_ = bh >> 4;
    const int head = bh & 15;
    #pragma unroll
    for (int rc = 0; rc < 2; rc++) {
        #pragma unroll
        for (int r2 = 0; r2 < 2; r2++) {
            const float inv = 1.f / l_i[rc * 2 + r2];
            const int row = m0 + wrow + 16 * rc + g + r2 * 8;
            #pragma unroll
            for (int nt = 0; nt < 8; nt++) {
                float2 v;
                v.x = rna_tf32(o[rc][nt][r2 * 2]     * inv);
                v.y = rna_tf32(o[rc][nt][r2 * 2 + 1] * inv);
                *(float2*)&g_y[((size_t)(b_ * Tv + row)) * Cv + head * 64 + nt * 8 + 2 * tg] = v;
            }
        }
    }
}

// ---------------------------------------------------------------------------
extern "C" void kernel_launch(void* const* d_in, const int* in_sizes, int n_in,
                              void* d_out, int out_size)
{
    const float* x     = (const float*)d_in[0];
    const float* W_qkv = (const float*)d_in[1];
    const float* b_qkv = (const float*)d_in[2];
    const float* W_out = (const float*)d_in[3];
    const float* b_out = (const float*)d_in[4];
    float* out = (float*)d_out;

    float* xr;  cudaGetSymbolAddress((void**)&xr,  g_xr);
    float* wqT; cudaGetSymbolAddress((void**)&wqT, g_wqT);
    float* woT; cudaGetSymbolAddress((void**)&woT, g_woT);

    cudaFuncSetAttribute(attn_mma_kernel,
                         cudaFuncAttributeMaxDynamicSharedMemorySize, ATTN_SMEM);
    cudaFuncSetAttribute(gemm_mma<0>,
                         cudaFuncAttributeMaxDynamicSharedMemorySize, GEMM_SMEM);
    cudaFuncSetAttribute(gemm_mma<1>,
                         cudaFuncAttributeMaxDynamicSharedMemorySize, GEMM_SMEM);

    // prep: round x; transpose+round weights to [N][K]
    round_rna_kernel<<<2048, 256>>>((const float4*)x, (float4*)xr, Mrows * Cv / 4);
    transpose_rna_kernel<<<dim3(3 * Cv / 32, Cv / 32), dim3(32, 8)>>>(W_qkv, wqT, Cv, 3 * Cv);
    transpose_rna_kernel<<<dim3(Cv / 32, Cv / 32), dim3(32, 8)>>>(W_out, woT, Cv, Cv);

    // 1) QKV projection (full-ldmatrix tf32 MMA)
    gemm_mma<0><<<dim3(3 * Cv / 128, Mrows / 128), 256, GEMM_SMEM>>>(xr, wqT, b_qkv, nullptr);

    // 2) causal flash attention
    attn_mma_kernel<<<dim3(Tv / 128, Bv * Hv), 128, ATTN_SMEM>>>();

    // 3) output projection
    gemm_mma<1><<<dim3(Cv / 128, Mrows / 128), 256, GEMM_SMEM>>>(nullptr, woT, b_out, out);
}